// round 7
// baseline (speedup 1.0000x reference)
#include <cuda_runtime.h>
#include <cuda_bf16.h>
#include <math.h>

// Problem constants
#define BB 256   // batch
#define TT 64    // encoder seq len
#define HH 1024  // hidden
#define GG 4096  // 4*H
#define VV 128   // vocab
#define LL 32    // decoder len

// GEMM tiling
#define BM 64
#define BN 128
#define BK 16
#define PADA 66   // As row stride in floats (bank-conflict-free STS, 8B aligned rows)

// ---------------- device state (no allocations allowed) ----------------
__device__ float d_hbuf[2][BB * HH];
__device__ float d_cbuf[BB * HH];
__device__ float d_encX[VV * GG];   // packed: [v][k*4+g] = emb[v]@W[:,g*1024+k] + b
__device__ float d_decX[VV * GG];
__device__ int   d_tok[BB];

// ---------------- helpers ----------------
__device__ __forceinline__ unsigned long long dup2(float x) {
    unsigned long long r;
    unsigned xi = __float_as_uint(x);
    asm("mov.b64 %0, {%1, %1};" : "=l"(r) : "r"(xi));
    return r;
}
__device__ __forceinline__ void fma2(unsigned long long& d, unsigned long long a,
                                     unsigned long long b) {
    asm("fma.rn.f32x2 %0, %1, %2, %0;" : "+l"(d) : "l"(a), "l"(b));
}
__device__ __forceinline__ float2 unpack2(unsigned long long v) {
    unsigned lo, hi;
    asm("mov.b64 {%0, %1}, %2;" : "=r"(lo), "=r"(hi) : "l"(v));
    return make_float2(__uint_as_float(lo), __uint_as_float(hi));
}
__device__ __forceinline__ float sigmoidf_(float x) {
    return 1.0f / (1.0f + __expf(-x));
}
__device__ __forceinline__ float tanhf_(float x) {
    float a = fabsf(x);
    float e = __expf(2.0f * a);
    float t = 1.0f - 2.0f / (e + 1.0f);
    return copysignf(t, x);
}

// ---------------- init ----------------
__global__ void init_kernel() {
    int n = BB * HH;
    for (int i = blockIdx.x * blockDim.x + threadIdx.x; i < n;
         i += gridDim.x * blockDim.x) {
        d_hbuf[0][i] = 0.0f;
        d_cbuf[i]    = 0.0f;
    }
    if (blockIdx.x == 0 && threadIdx.x < BB) d_tok[threadIdx.x] = VV - 1;  // delimiter
}

// ---------------- table: Xp[v][k*4+g] = emb[v]@W[:,g*1024+k] + b[g*1024+k] ----------------
// grid 128 CTAs x 256 threads. CTA owns 32 original columns; thread owns 1 col x 16 vocab rows.
__global__ __launch_bounds__(256, 1) void table_kernel(
    const float* __restrict__ emb, const float* __restrict__ W,
    const float* __restrict__ bias, int which) {
    float* Xp = which ? d_decX : d_encX;
    __shared__ __align__(16) float semb[32][VV];   // [r][v]
    int tid = threadIdx.x;
    int c = blockIdx.x * 32 + (tid & 31);          // original column 0..4095
    int vg = tid >> 5;                             // 0..7 -> 16 vocab rows

    float acc[16];
#pragma unroll
    for (int j = 0; j < 16; j++) acc[j] = 0.0f;

    for (int r0 = 0; r0 < HH; r0 += 32) {
#pragma unroll
        for (int j = 0; j < 4; j++) {
            int idx4 = tid + 256 * j;              // 0..1023 float4s
            int v  = idx4 >> 3;                    // 0..127
            int rq = idx4 & 7;                     // 0..7
            float4 t4 = *(const float4*)&emb[(size_t)v * HH + r0 + (rq << 2)];
            semb[(rq << 2) + 0][v] = t4.x;
            semb[(rq << 2) + 1][v] = t4.y;
            semb[(rq << 2) + 2][v] = t4.z;
            semb[(rq << 2) + 3][v] = t4.w;
        }
        __syncthreads();
#pragma unroll 8
        for (int r = 0; r < 32; r++) {
            float w = W[(size_t)(r0 + r) * GG + c];
            const float* sp = &semb[r][vg << 4];
#pragma unroll
            for (int j = 0; j < 16; j++) acc[j] += sp[j] * w;
        }
        __syncthreads();
    }
    int k = c & (HH - 1);
    int g = c >> 10;
    float bv = bias[c];
#pragma unroll
    for (int j = 0; j < 16; j++) {
        int v = (vg << 4) + j;
        Xp[(size_t)v * GG + (k << 2) + g] = acc[j] + bv;
    }
}

// ---------------- fused LSTM step: z = h@U + Xp[tok]; gates; masked state update ------------
// grid (32, 4), 256 threads. CTA tile: 64 rows x 128 packed cols (= 32 hidden units x 4 gates)
__global__ __launch_bounds__(256, 1) void lstm_step_kernel(
    const float* __restrict__ U, int xp_dec,
    const int* __restrict__ tokptr, int tokstride, int tok_mode, int parity) {
    const float* __restrict__ hin  = d_hbuf[parity];
    float* __restrict__ hout       = d_hbuf[parity ^ 1];
    const float* __restrict__ Xp   = xp_dec ? d_decX : d_encX;

    __shared__ __align__(16) float As[2][BK][PADA];
    __shared__ __align__(16) float Bs[2][BK][BN];
    __shared__ int stok[BM];

    int tid = threadIdx.x;
    int bm0 = blockIdx.y * BM;
    int bn0 = blockIdx.x * BN;     // packed col base (multiple of 128)
    int ku0 = bn0 >> 2;            // hidden-unit base

    // tokens for this row tile
    if (tid < BM) {
        if (tok_mode) stok[tid] = d_tok[bm0 + tid];
        else          stok[tid] = tokptr[(size_t)(bm0 + tid) * tokstride];
    }

    int tx = tid & 31;             // 32 col groups of 4 packed cols
    int ty = tid >> 5;             // 8 row groups of 8 rows

    // A staging: thread -> (row, k-quad)
    int a_row = tid >> 2;
    int a_kq  = tid & 3;
    const float* a_src = hin + (size_t)(bm0 + a_row) * HH + (a_kq << 2);

    unsigned long long acc[4][4];
#pragma unroll
    for (int i = 0; i < 4; i++)
#pragma unroll
        for (int j = 0; j < 4; j++) acc[i][j] = 0ull;

    float4 ga;
    float  gb[8];

    // prefetch tile 0
    {
        ga = *(const float4*)(a_src + 0);
#pragma unroll
        for (int j = 0; j < 8; j++) {
            int idx = tid + 256 * j;
            int k = idx >> 7, pc = idx & 127;
            int ku = pc >> 2, g = pc & 3;
            gb[j] = U[(size_t)(0 + k) * GG + g * 1024 + ku0 + ku];
        }
        As[0][(a_kq << 2) + 0][a_row] = ga.x;
        As[0][(a_kq << 2) + 1][a_row] = ga.y;
        As[0][(a_kq << 2) + 2][a_row] = ga.z;
        As[0][(a_kq << 2) + 3][a_row] = ga.w;
#pragma unroll
        for (int j = 0; j < 8; j++) {
            int idx = tid + 256 * j;
            Bs[0][idx >> 7][idx & 127] = gb[j];
        }
    }
    __syncthreads();

    const int NIT = HH / BK;  // 64
    for (int it = 0; it < NIT; it++) {
        if (it + 1 < NIT) {
            int k0 = (it + 1) * BK;
            ga = *(const float4*)(a_src + k0);
#pragma unroll
            for (int j = 0; j < 8; j++) {
                int idx = tid + 256 * j;
                int k = idx >> 7, pc = idx & 127;
                int ku = pc >> 2, g = pc & 3;
                gb[j] = U[(size_t)(k0 + k) * GG + g * 1024 + ku0 + ku];
            }
        }
        int buf = it & 1;
#pragma unroll
        for (int k = 0; k < BK; k++) {
            const unsigned long long* ap =
                reinterpret_cast<const unsigned long long*>(&As[buf][k][ty << 3]);
            unsigned long long a0 = ap[0], a1 = ap[1], a2 = ap[2], a3 = ap[3];
            float4 b4 = *reinterpret_cast<const float4*>(&Bs[buf][k][tx << 2]);
            unsigned long long b0 = dup2(b4.x), b1 = dup2(b4.y);
            unsigned long long b2 = dup2(b4.z), b3 = dup2(b4.w);
            fma2(acc[0][0], a0, b0); fma2(acc[0][1], a0, b1);
            fma2(acc[0][2], a0, b2); fma2(acc[0][3], a0, b3);
            fma2(acc[1][0], a1, b0); fma2(acc[1][1], a1, b1);
            fma2(acc[1][2], a1, b2); fma2(acc[1][3], a1, b3);
            fma2(acc[2][0], a2, b0); fma2(acc[2][1], a2, b1);
            fma2(acc[2][2], a2, b2); fma2(acc[2][3], a2, b3);
            fma2(acc[3][0], a3, b0); fma2(acc[3][1], a3, b1);
            fma2(acc[3][2], a3, b2); fma2(acc[3][3], a3, b3);
        }
        if (it + 1 < NIT) {
            int nb = (it + 1) & 1;
            As[nb][(a_kq << 2) + 0][a_row] = ga.x;
            As[nb][(a_kq << 2) + 1][a_row] = ga.y;
            As[nb][(a_kq << 2) + 2][a_row] = ga.z;
            As[nb][(a_kq << 2) + 3][a_row] = ga.w;
#pragma unroll
            for (int j = 0; j < 8; j++) {
                int idx = tid + 256 * j;
                Bs[nb][idx >> 7][idx & 127] = gb[j];
            }
        }
        __syncthreads();
    }

    // epilogue: gates + masked state update
    int pcg = bn0 + (tx << 2);   // packed col base for this thread
    int kg  = pcg >> 2;          // hidden unit index
#pragma unroll
    for (int rp = 0; rp < 4; rp++) {
        float2 zi2 = unpack2(acc[rp][0]);
        float2 zf2 = unpack2(acc[rp][1]);
        float2 zg2 = unpack2(acc[rp][2]);
        float2 zo2 = unpack2(acc[rp][3]);
#pragma unroll
        for (int hh = 0; hh < 2; hh++) {
            int row = (ty << 3) + (rp << 1) + hh;
            int b = bm0 + row;
            int tokb = stok[row];
            float4 xv = *(const float4*)&Xp[(size_t)tokb * GG + pcg];
            float zi = (hh ? zi2.y : zi2.x) + xv.x;
            float zf = (hh ? zf2.y : zf2.x) + xv.y;
            float zg = (hh ? zg2.y : zg2.x) + xv.z;
            float zo = (hh ? zo2.y : zo2.x) + xv.w;
            float ig = sigmoidf_(zi);
            float fg = sigmoidf_(zf);
            float gg = tanhf_(zg);
            float og = sigmoidf_(zo);
            size_t off = (size_t)b * HH + kg;
            float cold = d_cbuf[off];
            float c2 = fg * cold + ig * gg;
            float h2 = og * tanhf_(c2);
            if (tokb != 0) {
                d_cbuf[off] = c2;
                hout[off]   = h2;
            } else {
                hout[off] = hin[off];
            }
        }
    }
}

// ---------------- decoder output: logits->softmax->argmax, store y & tok -------------------
// grid 64 CTAs x 256 threads; CTA owns 4 batch rows.
__global__ __launch_bounds__(256, 2) void dec_out_kernel(
    const float* __restrict__ outW, const float* __restrict__ outb,
    float* __restrict__ dout, int out_size, int t, int parity) {
    const float* __restrict__ h = d_hbuf[parity];
    __shared__ __align__(16) float sh[4][HH];
    __shared__ float slog[4][VV];
    __shared__ float sexp[4][VV];
    __shared__ float ssum[4];
    __shared__ int   stk[4];

    int tid = threadIdx.x;
    int b0 = blockIdx.x * 4;

#pragma unroll
    for (int j = 0; j < 4; j++) {
        int idx4 = tid + 256 * j;          // 0..1023 float4s
        int row = idx4 >> 8;
        int c4 = idx4 & 255;
        *(float4*)&sh[row][c4 << 2] =
            *(const float4*)&h[(size_t)(b0 + row) * HH + (c4 << 2)];
    }
    __syncthreads();

    int v = tid & 127;
    int half = tid >> 7;
    float a0 = 0.0f, a1 = 0.0f;
    const float* s0 = sh[half * 2];
    const float* s1 = sh[half * 2 + 1];
#pragma unroll 8
    for (int k = 0; k < HH; k++) {
        float w = outW[(size_t)k * VV + v];
        a0 += s0[k] * w;
        a1 += s1[k] * w;
    }
    float bv = outb[v];
    slog[half * 2][v]     = a0 + bv;
    slog[half * 2 + 1][v] = a1 + bv;
    __syncthreads();

    if (tid < 128) {                       // warps 0..3, one row each
        int rw = tid >> 5;
        int lane = tid & 31;
        float m = -3.4e38f;
        int am = VV;
#pragma unroll
        for (int i = 0; i < 4; i++) {
            int vv = lane + (i << 5);
            float x = slog[rw][vv];
            if (x > m || (x == m && vv < am)) { m = x; am = vv; }
        }
#pragma unroll
        for (int off = 16; off; off >>= 1) {
            float om = __shfl_down_sync(0xffffffffu, m, off);
            int   oa = __shfl_down_sync(0xffffffffu, am, off);
            if (om > m || (om == m && oa < am)) { m = om; am = oa; }
        }
        m  = __shfl_sync(0xffffffffu, m, 0);
        am = __shfl_sync(0xffffffffu, am, 0);
        float s = 0.0f;
#pragma unroll
        for (int i = 0; i < 4; i++) {
            int vv = lane + (i << 5);
            float e = __expf(slog[rw][vv] - m);
            sexp[rw][vv] = e;
            s += e;
        }
#pragma unroll
        for (int off = 16; off; off >>= 1) s += __shfl_xor_sync(0xffffffffu, s, off);
        if (lane == 0) {
            ssum[rw] = s;
            stk[rw]  = am;
            d_tok[b0 + rw] = am;
        }
    }
    __syncthreads();

#pragma unroll
    for (int j = 0; j < 2; j++) {
        int idx = tid + 256 * j;           // 0..511
        int rw = idx >> 7;
        int vv = idx & 127;
        dout[((size_t)(b0 + rw) * LL + t) * VV + vv] = sexp[rw][vv] / ssum[rw];
    }
    if (out_size >= BB * LL * VV + LL * BB && tid < 4) {
        dout[(size_t)BB * LL * VV + (size_t)t * BB + (b0 + tid)] = (float)stk[tid];
    }
}

// ---------------- launcher ----------------
extern "C" void kernel_launch(void* const* d_in, const int* in_sizes, int n_in,
                              void* d_out, int out_size) {
    int idx = 0;
    const int* inputs = (const int*)d_in[idx++];
    if (idx < n_in && in_sizes[idx] == 1) idx++;  // skip max_len scalar if present
    const float* enc_emb = (const float*)d_in[idx++];
    const float* enc_W   = (const float*)d_in[idx++];
    const float* enc_U   = (const float*)d_in[idx++];
    const float* enc_b   = (const float*)d_in[idx++];
    const float* dec_emb = (const float*)d_in[idx++];
    const float* dec_W   = (const float*)d_in[idx++];
    const float* dec_U   = (const float*)d_in[idx++];
    const float* dec_b   = (const float*)d_in[idx++];
    const float* out_W   = (const float*)d_in[idx++];
    const float* out_b   = (const float*)d_in[idx++];
    float* dout = (float*)d_out;

    init_kernel<<<256, 256>>>();
    table_kernel<<<128, 256>>>(enc_emb, enc_W, enc_b, 0);
    table_kernel<<<128, 256>>>(dec_emb, dec_W, dec_b, 1);

    dim3 grid(GG / BN, BB / BM);  // (32, 4)
    int par = 0;
    for (int t = 0; t < TT; t++) {
        lstm_step_kernel<<<grid, 256>>>(enc_U, 0, inputs + t, TT, 0, par);
        par ^= 1;
    }
    for (int s = 0; s < LL; s++) {
        lstm_step_kernel<<<grid, 256>>>(dec_U, 1, (const int*)0, 1, 1, par);
        par ^= 1;
        dec_out_kernel<<<64, 256>>>(out_W, out_b, dout, out_size, s, par);
    }
}

// round 8
// speedup vs baseline: 1.0100x; 1.0100x over previous
#include <cuda_runtime.h>
#include <cuda_bf16.h>
#include <math.h>

// Problem constants
#define BB 256   // batch
#define TT 64    // encoder seq len
#define HH 1024  // hidden
#define GG 4096  // 4*H
#define VV 128   // vocab
#define LL 32    // decoder len

// GEMM tiling
#define BM 64
#define BN 128
#define BK 16
#define PADA 66   // As row stride in floats (bank-conflict-free STS, 8B aligned rows)

// ---------------- device state (no allocations allowed) ----------------
__device__ float d_hbuf[2][BB * HH];
__device__ float d_cbuf[BB * HH];
__device__ float d_encX[VV * GG];   // packed: [v][k*4+g] = emb[v]@W[:,g*1024+k] + b
__device__ float d_decX[VV * GG];
__device__ int   d_tok[BB];

// ---------------- helpers ----------------
__device__ __forceinline__ unsigned long long dup2(float x) {
    unsigned long long r;
    unsigned xi = __float_as_uint(x);
    asm("mov.b64 %0, {%1, %1};" : "=l"(r) : "r"(xi));
    return r;
}
__device__ __forceinline__ void fma2(unsigned long long& d, unsigned long long a,
                                     unsigned long long b) {
    asm("fma.rn.f32x2 %0, %1, %2, %0;" : "+l"(d) : "l"(a), "l"(b));
}
__device__ __forceinline__ float2 unpack2(unsigned long long v) {
    unsigned lo, hi;
    asm("mov.b64 {%0, %1}, %2;" : "=r"(lo), "=r"(hi) : "l"(v));
    return make_float2(__uint_as_float(lo), __uint_as_float(hi));
}
__device__ __forceinline__ float sigmoidf_(float x) {
    return 1.0f / (1.0f + __expf(-x));
}
__device__ __forceinline__ float tanhf_(float x) {
    float a = fabsf(x);
    float e = __expf(2.0f * a);
    float t = 1.0f - 2.0f / (e + 1.0f);
    return copysignf(t, x);
}

// ---------------- init ----------------
__global__ void init_kernel() {
    int n = BB * HH;
    for (int i = blockIdx.x * blockDim.x + threadIdx.x; i < n;
         i += gridDim.x * blockDim.x) {
        d_hbuf[0][i] = 0.0f;
        d_cbuf[i]    = 0.0f;
    }
    if (blockIdx.x == 0 && threadIdx.x < BB) d_tok[threadIdx.x] = VV - 1;  // delimiter
}

// ---------------- table: Xp[v][k*4+g] = emb[v]@W[:,g*1024+k] + b[g*1024+k] ----------------
// grid 128 CTAs x 256 threads. CTA owns 32 original columns; thread owns 1 col x 16 vocab rows.
__global__ __launch_bounds__(256, 1) void table_kernel(
    const float* __restrict__ emb, const float* __restrict__ W,
    const float* __restrict__ bias, int which) {
    float* Xp = which ? d_decX : d_encX;
    __shared__ __align__(16) float semb[32][VV];   // [r][v]
    int tid = threadIdx.x;
    int c = blockIdx.x * 32 + (tid & 31);          // original column 0..4095
    int vg = tid >> 5;                             // 0..7 -> 16 vocab rows

    float acc[16];
#pragma unroll
    for (int j = 0; j < 16; j++) acc[j] = 0.0f;

    for (int r0 = 0; r0 < HH; r0 += 32) {
#pragma unroll
        for (int j = 0; j < 4; j++) {
            int idx4 = tid + 256 * j;              // 0..1023 float4s
            int v  = idx4 >> 3;                    // 0..127
            int rq = idx4 & 7;                     // 0..7
            float4 t4 = *(const float4*)&emb[(size_t)v * HH + r0 + (rq << 2)];
            semb[(rq << 2) + 0][v] = t4.x;
            semb[(rq << 2) + 1][v] = t4.y;
            semb[(rq << 2) + 2][v] = t4.z;
            semb[(rq << 2) + 3][v] = t4.w;
        }
        __syncthreads();
#pragma unroll 8
        for (int r = 0; r < 32; r++) {
            float w = W[(size_t)(r0 + r) * GG + c];
            const float* sp = &semb[r][vg << 4];
#pragma unroll
            for (int j = 0; j < 16; j++) acc[j] += sp[j] * w;
        }
        __syncthreads();
    }
    int k = c & (HH - 1);
    int g = c >> 10;
    float bv = bias[c];
#pragma unroll
    for (int j = 0; j < 16; j++) {
        int v = (vg << 4) + j;
        Xp[(size_t)v * GG + (k << 2) + g] = acc[j] + bv;
    }
}

// ---------------- fused LSTM step: z = h@U + Xp[tok]; gates; masked state update ------------
// grid (32, 4), 256 threads. CTA tile: 64 rows x 128 packed cols (= 32 hidden units x 4 gates)
__global__ __launch_bounds__(256, 1) void lstm_step_kernel(
    const float* __restrict__ U, int xp_dec,
    const int* __restrict__ tokptr, int tokstride, int tok_mode, int parity) {
    const float* __restrict__ hin  = d_hbuf[parity];
    float* __restrict__ hout       = d_hbuf[parity ^ 1];
    const float* __restrict__ Xp   = xp_dec ? d_decX : d_encX;

    __shared__ __align__(16) float As[2][BK][PADA];
    __shared__ __align__(16) float Bs[2][BK][BN];
    __shared__ int stok[BM];

    int tid = threadIdx.x;
    int bm0 = blockIdx.y * BM;
    int bn0 = blockIdx.x * BN;     // packed col base (multiple of 128)
    int ku0 = bn0 >> 2;            // hidden-unit base

    // tokens for this row tile
    if (tid < BM) {
        if (tok_mode) stok[tid] = d_tok[bm0 + tid];
        else          stok[tid] = tokptr[(size_t)(bm0 + tid) * tokstride];
    }

    int tx = tid & 31;             // 32 col groups of 4 packed cols
    int ty = tid >> 5;             // 8 row groups of 8 rows

    // A staging: thread -> (row, k-quad)
    int a_row = tid >> 2;
    int a_kq  = tid & 3;
    const float* a_src = hin + (size_t)(bm0 + a_row) * HH + (a_kq << 2);

    unsigned long long acc[4][4];
#pragma unroll
    for (int i = 0; i < 4; i++)
#pragma unroll
        for (int j = 0; j < 4; j++) acc[i][j] = 0ull;

    float4 ga;
    float  gb[8];

    // prefetch tile 0
    {
        ga = *(const float4*)(a_src + 0);
#pragma unroll
        for (int j = 0; j < 8; j++) {
            int idx = tid + 256 * j;
            int k = idx >> 7, pc = idx & 127;
            int ku = pc >> 2, g = pc & 3;
            gb[j] = U[(size_t)(0 + k) * GG + g * 1024 + ku0 + ku];
        }
        As[0][(a_kq << 2) + 0][a_row] = ga.x;
        As[0][(a_kq << 2) + 1][a_row] = ga.y;
        As[0][(a_kq << 2) + 2][a_row] = ga.z;
        As[0][(a_kq << 2) + 3][a_row] = ga.w;
#pragma unroll
        for (int j = 0; j < 8; j++) {
            int idx = tid + 256 * j;
            Bs[0][idx >> 7][idx & 127] = gb[j];
        }
    }
    __syncthreads();

    const int NIT = HH / BK;  // 64
    for (int it = 0; it < NIT; it++) {
        if (it + 1 < NIT) {
            int k0 = (it + 1) * BK;
            ga = *(const float4*)(a_src + k0);
#pragma unroll
            for (int j = 0; j < 8; j++) {
                int idx = tid + 256 * j;
                int k = idx >> 7, pc = idx & 127;
                int ku = pc >> 2, g = pc & 3;
                gb[j] = U[(size_t)(k0 + k) * GG + g * 1024 + ku0 + ku];
            }
        }
        int buf = it & 1;
#pragma unroll
        for (int k = 0; k < BK; k++) {
            const unsigned long long* ap =
                reinterpret_cast<const unsigned long long*>(&As[buf][k][ty << 3]);
            unsigned long long a0 = ap[0], a1 = ap[1], a2 = ap[2], a3 = ap[3];
            float4 b4 = *reinterpret_cast<const float4*>(&Bs[buf][k][tx << 2]);
            unsigned long long b0 = dup2(b4.x), b1 = dup2(b4.y);
            unsigned long long b2 = dup2(b4.z), b3 = dup2(b4.w);
            fma2(acc[0][0], a0, b0); fma2(acc[0][1], a0, b1);
            fma2(acc[0][2], a0, b2); fma2(acc[0][3], a0, b3);
            fma2(acc[1][0], a1, b0); fma2(acc[1][1], a1, b1);
            fma2(acc[1][2], a1, b2); fma2(acc[1][3], a1, b3);
            fma2(acc[2][0], a2, b0); fma2(acc[2][1], a2, b1);
            fma2(acc[2][2], a2, b2); fma2(acc[2][3], a2, b3);
            fma2(acc[3][0], a3, b0); fma2(acc[3][1], a3, b1);
            fma2(acc[3][2], a3, b2); fma2(acc[3][3], a3, b3);
        }
        if (it + 1 < NIT) {
            int nb = (it + 1) & 1;
            As[nb][(a_kq << 2) + 0][a_row] = ga.x;
            As[nb][(a_kq << 2) + 1][a_row] = ga.y;
            As[nb][(a_kq << 2) + 2][a_row] = ga.z;
            As[nb][(a_kq << 2) + 3][a_row] = ga.w;
#pragma unroll
            for (int j = 0; j < 8; j++) {
                int idx = tid + 256 * j;
                Bs[nb][idx >> 7][idx & 127] = gb[j];
            }
        }
        __syncthreads();
    }

    // epilogue: gates + masked state update
    int pcg = bn0 + (tx << 2);   // packed col base for this thread
    int kg  = pcg >> 2;          // hidden unit index
#pragma unroll
    for (int rp = 0; rp < 4; rp++) {
        float2 zi2 = unpack2(acc[rp][0]);
        float2 zf2 = unpack2(acc[rp][1]);
        float2 zg2 = unpack2(acc[rp][2]);
        float2 zo2 = unpack2(acc[rp][3]);
#pragma unroll
        for (int hh = 0; hh < 2; hh++) {
            int row = (ty << 3) + (rp << 1) + hh;
            int b = bm0 + row;
            int tokb = stok[row];
            float4 xv = *(const float4*)&Xp[(size_t)tokb * GG + pcg];
            float zi = (hh ? zi2.y : zi2.x) + xv.x;
            float zf = (hh ? zf2.y : zf2.x) + xv.y;
            float zg = (hh ? zg2.y : zg2.x) + xv.z;
            float zo = (hh ? zo2.y : zo2.x) + xv.w;
            float ig = sigmoidf_(zi);
            float fg = sigmoidf_(zf);
            float gg = tanhf_(zg);
            float og = sigmoidf_(zo);
            size_t off = (size_t)b * HH + kg;
            float cold = d_cbuf[off];
            float c2 = fg * cold + ig * gg;
            float h2 = og * tanhf_(c2);
            if (tokb != 0) {
                d_cbuf[off] = c2;
                hout[off]   = h2;
            } else {
                hout[off] = hin[off];
            }
        }
    }
}

// ---------------- decoder output: logits->softmax->argmax, store y & tok -------------------
// grid 64 CTAs x 256 threads; CTA owns 4 batch rows.
__global__ __launch_bounds__(256, 2) void dec_out_kernel(
    const float* __restrict__ outW, const float* __restrict__ outb,
    float* __restrict__ dout, int out_size, int t, int parity) {
    const float* __restrict__ h = d_hbuf[parity];
    __shared__ __align__(16) float sh[4][HH];
    __shared__ float slog[4][VV];
    __shared__ float sexp[4][VV];
    __shared__ float ssum[4];
    __shared__ int   stk[4];

    int tid = threadIdx.x;
    int b0 = blockIdx.x * 4;

#pragma unroll
    for (int j = 0; j < 4; j++) {
        int idx4 = tid + 256 * j;          // 0..1023 float4s
        int row = idx4 >> 8;
        int c4 = idx4 & 255;
        *(float4*)&sh[row][c4 << 2] =
            *(const float4*)&h[(size_t)(b0 + row) * HH + (c4 << 2)];
    }
    __syncthreads();

    int v = tid & 127;
    int half = tid >> 7;
    float a0 = 0.0f, a1 = 0.0f;
    const float* s0 = sh[half * 2];
    const float* s1 = sh[half * 2 + 1];
#pragma unroll 8
    for (int k = 0; k < HH; k++) {
        float w = outW[(size_t)k * VV + v];
        a0 += s0[k] * w;
        a1 += s1[k] * w;
    }
    float bv = outb[v];
    slog[half * 2][v]     = a0 + bv;
    slog[half * 2 + 1][v] = a1 + bv;
    __syncthreads();

    if (tid < 128) {                       // warps 0..3, one row each
        int rw = tid >> 5;
        int lane = tid & 31;
        float m = -3.4e38f;
        int am = VV;
#pragma unroll
        for (int i = 0; i < 4; i++) {
            int vv = lane + (i << 5);
            float x = slog[rw][vv];
            if (x > m || (x == m && vv < am)) { m = x; am = vv; }
        }
#pragma unroll
        for (int off = 16; off; off >>= 1) {
            float om = __shfl_down_sync(0xffffffffu, m, off);
            int   oa = __shfl_down_sync(0xffffffffu, am, off);
            if (om > m || (om == m && oa < am)) { m = om; am = oa; }
        }
        m  = __shfl_sync(0xffffffffu, m, 0);
        am = __shfl_sync(0xffffffffu, am, 0);
        float s = 0.0f;
#pragma unroll
        for (int i = 0; i < 4; i++) {
            int vv = lane + (i << 5);
            float e = __expf(slog[rw][vv] - m);
            sexp[rw][vv] = e;
            s += e;
        }
#pragma unroll
        for (int off = 16; off; off >>= 1) s += __shfl_xor_sync(0xffffffffu, s, off);
        if (lane == 0) {
            ssum[rw] = s;
            stk[rw]  = am;
            d_tok[b0 + rw] = am;
        }
    }
    __syncthreads();

#pragma unroll
    for (int j = 0; j < 2; j++) {
        int idx = tid + 256 * j;           // 0..511
        int rw = idx >> 7;
        int vv = idx & 127;
        dout[((size_t)(b0 + rw) * LL + t) * VV + vv] = sexp[rw][vv] / ssum[rw];
    }
    if (out_size >= BB * LL * VV + LL * BB && tid < 4) {
        dout[(size_t)BB * LL * VV + (size_t)t * BB + (b0 + tid)] = (float)stk[tid];
    }
}

// ---------------- launcher ----------------
extern "C" void kernel_launch(void* const* d_in, const int* in_sizes, int n_in,
                              void* d_out, int out_size) {
    int idx = 0;
    const int* inputs = (const int*)d_in[idx++];
    if (idx < n_in && in_sizes[idx] == 1) idx++;  // skip max_len scalar if present
    const float* enc_emb = (const float*)d_in[idx++];
    const float* enc_W   = (const float*)d_in[idx++];
    const float* enc_U   = (const float*)d_in[idx++];
    const float* enc_b   = (const float*)d_in[idx++];
    const float* dec_emb = (const float*)d_in[idx++];
    const float* dec_W   = (const float*)d_in[idx++];
    const float* dec_U   = (const float*)d_in[idx++];
    const float* dec_b   = (const float*)d_in[idx++];
    const float* out_W   = (const float*)d_in[idx++];
    const float* out_b   = (const float*)d_in[idx++];
    float* dout = (float*)d_out;

    init_kernel<<<256, 256>>>();
    table_kernel<<<128, 256>>>(enc_emb, enc_W, enc_b, 0);
    table_kernel<<<128, 256>>>(dec_emb, dec_W, dec_b, 1);

    dim3 grid(GG / BN, BB / BM);  // (32, 4)
    int par = 0;
    for (int t = 0; t < TT; t++) {
        lstm_step_kernel<<<grid, 256>>>(enc_U, 0, inputs + t, TT, 0, par);
        par ^= 1;
    }
    for (int s = 0; s < LL; s++) {
        lstm_step_kernel<<<grid, 256>>>(dec_U, 1, (const int*)0, 1, 1, par);
        par ^= 1;
        dec_out_kernel<<<64, 256>>>(out_W, out_b, dout, out_size, s, par);
    }
}

// round 10
// speedup vs baseline: 1.6272x; 1.6111x over previous
#include <cuda_runtime.h>
#include <cuda_bf16.h>
#include <math.h>
#include <stdint.h>

#define BB 256
#define TT 64
#define HH 1024
#define GG 4096
#define VV 128
#define LL 32

// ---------------- device state (no allocations allowed) ----------------
__device__ __align__(16) float d_hbuf[2][BB * HH];           // fp32 h
__device__ __align__(16) __nv_bfloat16 d_hbb[2][BB * HH];    // bf16 big part of h
__device__ __align__(16) __nv_bfloat16 d_hsb[2][BB * HH];    // bf16 residual of h
__device__ __align__(16) float d_cbuf[BB * HH];
__device__ __align__(16) float d_encX[VV * GG];              // [v][ku*4+g] = emb@W + b
__device__ __align__(16) float d_decX[VV * GG];
__device__ int d_tok[BB];
__device__ __align__(16) __nv_bfloat16 d_Ubb[2][(size_t)GG * HH];  // [which][pc][k] big
__device__ __align__(16) __nv_bfloat16 d_Usb[2][(size_t)GG * HH];  // residual

// ---------------- helpers ----------------
__device__ __forceinline__ float sigmoidf_(float x) { return 1.0f / (1.0f + __expf(-x)); }
__device__ __forceinline__ float tanhf_(float x) {
    float a = fabsf(x);
    float e = __expf(2.0f * a);
    return copysignf(1.0f - 2.0f / (e + 1.0f), x);
}
__device__ __forceinline__ uint32_t smem_u32(const void* p) {
    uint32_t a;
    asm("{ .reg .u64 t; cvta.to.shared.u64 t, %1; cvt.u32.u64 %0, t; }" : "=r"(a) : "l"(p));
    return a;
}
__device__ __forceinline__ void cpasync16(uint32_t dst, const void* src) {
    asm volatile("cp.async.cg.shared.global [%0], [%1], 16;"
                 :: "r"(dst), "l"(__cvta_generic_to_global(src)) : "memory");
}
__device__ __forceinline__ void mma16816(float* c, const uint32_t* a, const uint32_t* b) {
    asm volatile(
        "mma.sync.aligned.m16n8k16.row.col.f32.bf16.bf16.f32 "
        "{%0,%1,%2,%3}, {%4,%5,%6,%7}, {%8,%9}, {%0,%1,%2,%3};"
        : "+f"(c[0]), "+f"(c[1]), "+f"(c[2]), "+f"(c[3])
        : "r"(a[0]), "r"(a[1]), "r"(a[2]), "r"(a[3]), "r"(b[0]), "r"(b[1]));
}

// ---------------- init ----------------
__global__ void init_kernel() {
    int n = BB * HH;
    __nv_bfloat16 z = __float2bfloat16(0.0f);
    for (int i = blockIdx.x * blockDim.x + threadIdx.x; i < n; i += gridDim.x * blockDim.x) {
        d_hbuf[0][i] = 0.0f;
        d_hbb[0][i] = z;
        d_hsb[0][i] = z;
        d_cbuf[i] = 0.0f;
    }
    if (blockIdx.x == 0 && threadIdx.x < BB) d_tok[threadIdx.x] = VV - 1;
}

// ---------------- table: Xp[v][ku*4+g] = emb[v]@W[:,g*1024+ku] + b ----------------
__global__ __launch_bounds__(256, 1) void table_kernel(
    const float* __restrict__ emb, const float* __restrict__ W,
    const float* __restrict__ bias, int which) {
    float* Xp = which ? d_decX : d_encX;
    __shared__ __align__(16) float semb[32][VV];
    int tid = threadIdx.x;
    int c = blockIdx.x * 32 + (tid & 31);
    int vg = tid >> 5;
    float acc[16];
#pragma unroll
    for (int j = 0; j < 16; j++) acc[j] = 0.0f;
    for (int r0 = 0; r0 < HH; r0 += 32) {
#pragma unroll
        for (int j = 0; j < 4; j++) {
            int idx4 = tid + 256 * j;
            int v = idx4 >> 3, rq = idx4 & 7;
            float4 t4 = *(const float4*)&emb[(size_t)v * HH + r0 + (rq << 2)];
            semb[(rq << 2) + 0][v] = t4.x;
            semb[(rq << 2) + 1][v] = t4.y;
            semb[(rq << 2) + 2][v] = t4.z;
            semb[(rq << 2) + 3][v] = t4.w;
        }
        __syncthreads();
#pragma unroll 8
        for (int r = 0; r < 32; r++) {
            float w = W[(size_t)(r0 + r) * GG + c];
            const float* sp = &semb[r][vg << 4];
#pragma unroll
            for (int j = 0; j < 16; j++) acc[j] += sp[j] * w;
        }
        __syncthreads();
    }
    int k = c & (HH - 1), g = c >> 10;
    float bv = bias[c];
#pragma unroll
    for (int j = 0; j < 16; j++) {
        int v = (vg << 4) + j;
        Xp[(size_t)v * GG + (k << 2) + g] = acc[j] + bv;
    }
}

// ---------------- pack U: Upk[ku*4+g][k] = U[k][g*1024+ku], bf16 split ----------------
__global__ __launch_bounds__(256, 4) void pack_kernel(const float* __restrict__ U, int which) {
    __shared__ float s[32][33];
    int tid = threadIdx.x;
    int k0 = blockIdx.x * 32;
    int c0 = blockIdx.y * 32;
#pragma unroll
    for (int j = 0; j < 4; j++) {
        int idx = tid + 256 * j;
        int r = idx >> 5, ci = idx & 31;
        s[r][ci] = U[(size_t)(k0 + r) * GG + c0 + ci];
    }
    __syncthreads();
    int g = c0 >> 10;
    int ku0 = c0 & (HH - 1);
    __nv_bfloat16* Ub = d_Ubb[which];
    __nv_bfloat16* Us = d_Usb[which];
#pragma unroll
    for (int j = 0; j < 4; j++) {
        int idx = tid + 256 * j;
        int ci = idx >> 5, r = idx & 31;
        float v = s[r][ci];
        __nv_bfloat16 bp = __float2bfloat16(v);
        size_t o = (size_t)((ku0 + ci) * 4 + g) * HH + (k0 + r);
        Ub[o] = bp;
        Us[o] = __float2bfloat16(v - __bfloat162float(bp));
    }
}

// ---------------- mma LSTM step ----------------
// grid (64,2), 256 threads = 8 warps (4 m-groups x 2 n-groups), warp tile 32x32.
// CTA: M=128 batch rows x N=64 packed cols, K=1024 in 32-wide cp.async chunks.
// z = hb@Ub + hb@Us + hs@Ub (bf16x3), epilogue via smem.
#define ASTR 40            // bf16 elems per smem row (80 B, 16B-multiple, conflict-free)
#define OFS_AB0 0u
#define OFS_AS0 10240u
#define OFS_BB0 20480u
#define OFS_BS0 25600u
#define BUFSZ   30720u
#define OFS_TOK 61440u
#define SMEM_BYTES 61952
#define ZSTR 68            // z epilogue stride (floats)

__device__ __forceinline__ void stage_chunk(
    uint32_t sb, int buf, int kc, int tid,
    const __nv_bfloat16* hb, const __nv_bfloat16* hs,
    const __nv_bfloat16* Ub, const __nv_bfloat16* Us, int bm0, int bn0) {
    uint32_t ab = sb + OFS_AB0 + buf * BUFSZ;
    uint32_t as = sb + OFS_AS0 + buf * BUFSZ;
    uint32_t bb = sb + OFS_BB0 + buf * BUFSZ;
    uint32_t bs = sb + OFS_BS0 + buf * BUFSZ;
    int kofs = kc * 32;
#pragma unroll
    for (int j = 0; j < 2; j++) {               // A: 128 rows x 64B (4 x 16B)
        int idx = tid + 256 * j;
        int row = idx >> 2, c16 = idx & 3;
        uint32_t d = (uint32_t)(row * (ASTR * 2) + c16 * 16);
        size_t go = (size_t)(bm0 + row) * HH + kofs + c16 * 8;
        cpasync16(ab + d, hb + go);
        cpasync16(as + d, hs + go);
    }
    {                                           // B: 64 rows x 64B
        int row = tid >> 2, c16 = tid & 3;
        uint32_t d = (uint32_t)(row * (ASTR * 2) + c16 * 16);
        size_t go = (size_t)(bn0 + row) * HH + kofs + c16 * 8;
        cpasync16(bb + d, Ub + go);
        cpasync16(bs + d, Us + go);
    }
}

__global__ __launch_bounds__(256, 1) void lstm_mma_kernel(
    int which, const int* __restrict__ tokptr, int tokstride, int tok_mode, int parity) {
    extern __shared__ char smem[];
    uint32_t sb = smem_u32(smem);
    int tid = threadIdx.x;
    int wid = tid >> 5, lane = tid & 31;
    int wm = wid & 3, wn = wid >> 2;            // warp tile: rows wm*32, cols wn*32
    int bn0 = blockIdx.x * 64;
    int bm0 = blockIdx.y * 128;

    const __nv_bfloat16* hb = d_hbb[parity];
    const __nv_bfloat16* hs = d_hsb[parity];
    const __nv_bfloat16* Ub = d_Ubb[which];
    const __nv_bfloat16* Us = d_Usb[which];
    int* stok = (int*)(smem + OFS_TOK);

    if (tid < 128)
        stok[tid] = tok_mode ? d_tok[bm0 + tid] : tokptr[(size_t)(bm0 + tid) * tokstride];

    float acc[2][4][4];
#pragma unroll
    for (int mt = 0; mt < 2; mt++)
#pragma unroll
        for (int nt = 0; nt < 4; nt++)
#pragma unroll
            for (int r = 0; r < 4; r++) acc[mt][nt][r] = 0.0f;

    int gq = lane >> 2;   // 0..7 (groupID)
    int tq = lane & 3;    // 0..3 (thread-in-group)

    stage_chunk(sb, 0, 0, tid, hb, hs, Ub, Us, bm0, bn0);
    asm volatile("cp.async.commit_group;" ::: "memory");

    for (int i = 0; i < 32; i++) {
        if (i + 1 < 32) {
            stage_chunk(sb, (i + 1) & 1, i + 1, tid, hb, hs, Ub, Us, bm0, bn0);
            asm volatile("cp.async.commit_group;" ::: "memory");
            asm volatile("cp.async.wait_group 1;" ::: "memory");
        } else {
            asm volatile("cp.async.wait_group 0;" ::: "memory");
        }
        __syncthreads();
        uint32_t abp = sb + OFS_AB0 + (i & 1) * BUFSZ;
        uint32_t asp = sb + OFS_AS0 + (i & 1) * BUFSZ;
        uint32_t bbp = sb + OFS_BB0 + (i & 1) * BUFSZ;
        uint32_t bsp = sb + OFS_BS0 + (i & 1) * BUFSZ;
#pragma unroll
        for (int ks = 0; ks < 2; ks++) {
            int kb = ks * 16 + 2 * tq;          // bf16 element offset of a0/b0 pair
            uint32_t ab[2][4], as2[2][4], bbr[4][2], bsr[4][2];
#pragma unroll
            for (int mt = 0; mt < 2; mt++) {
                int r0 = (wm * 32 + mt * 16 + gq) * (ASTR * 2);
                int r8 = r0 + 8 * (ASTR * 2);
                ab[mt][0] = *(const uint32_t*)(smem + (abp - sb) + r0 + kb * 2);
                ab[mt][1] = *(const uint32_t*)(smem + (abp - sb) + r8 + kb * 2);
                ab[mt][2] = *(const uint32_t*)(smem + (abp - sb) + r0 + (kb + 8) * 2);
                ab[mt][3] = *(const uint32_t*)(smem + (abp - sb) + r8 + (kb + 8) * 2);
                as2[mt][0] = *(const uint32_t*)(smem + (asp - sb) + r0 + kb * 2);
                as2[mt][1] = *(const uint32_t*)(smem + (asp - sb) + r8 + kb * 2);
                as2[mt][2] = *(const uint32_t*)(smem + (asp - sb) + r0 + (kb + 8) * 2);
                as2[mt][3] = *(const uint32_t*)(smem + (asp - sb) + r8 + (kb + 8) * 2);
            }
#pragma unroll
            for (int nt = 0; nt < 4; nt++) {
                int c0 = (wn * 32 + nt * 8 + gq) * (ASTR * 2);
                bbr[nt][0] = *(const uint32_t*)(smem + (bbp - sb) + c0 + kb * 2);
                bbr[nt][1] = *(const uint32_t*)(smem + (bbp - sb) + c0 + (kb + 8) * 2);
                bsr[nt][0] = *(const uint32_t*)(smem + (bsp - sb) + c0 + kb * 2);
                bsr[nt][1] = *(const uint32_t*)(smem + (bsp - sb) + c0 + (kb + 8) * 2);
            }
#pragma unroll
            for (int mt = 0; mt < 2; mt++)
#pragma unroll
                for (int nt = 0; nt < 4; nt++) {
                    mma16816(acc[mt][nt], ab[mt], bbr[nt]);
                    mma16816(acc[mt][nt], ab[mt], bsr[nt]);
                    mma16816(acc[mt][nt], as2[mt], bbr[nt]);
                }
        }
        __syncthreads();
    }

    // ---- epilogue: z -> smem -> gates ----
    float* z = (float*)smem;   // 128 x ZSTR floats = 34816 B (buffers dead now)
#pragma unroll
    for (int mt = 0; mt < 2; mt++) {
        int row0 = wm * 32 + mt * 16 + gq;
#pragma unroll
        for (int nt = 0; nt < 4; nt++) {
            int col = wn * 32 + nt * 8 + 2 * tq;
            *(float2*)&z[row0 * ZSTR + col] = make_float2(acc[mt][nt][0], acc[mt][nt][1]);
            *(float2*)&z[(row0 + 8) * ZSTR + col] = make_float2(acc[mt][nt][2], acc[mt][nt][3]);
        }
    }
    __syncthreads();

    int row = tid & 127;
    int ublk = tid >> 7;                 // 0..1 -> units ublk*8 .. +7
    int b = bm0 + row;
    int tok = stok[row];
    const float* Xp = which ? d_decX : d_encX;
    const float* hin = d_hbuf[parity];
    float* hout = d_hbuf[parity ^ 1];
    __nv_bfloat16* hbo = d_hbb[parity ^ 1];
    __nv_bfloat16* hso = d_hsb[parity ^ 1];

    if (tok != 0) {
#pragma unroll
        for (int j = 0; j < 8; j++) {
            int u = ublk * 8 + j;
            int kg = (bn0 >> 2) + u;
            float4 zv = *(const float4*)&z[row * ZSTR + u * 4];
            float4 xv = *(const float4*)&Xp[(size_t)tok * GG + bn0 + u * 4];
            float zi = zv.x + xv.x, zf = zv.y + xv.y;
            float zg = zv.z + xv.z, zo = zv.w + xv.w;
            size_t off = (size_t)b * HH + kg;
            float c2 = sigmoidf_(zf) * d_cbuf[off] + sigmoidf_(zi) * tanhf_(zg);
            float h2 = sigmoidf_(zo) * tanhf_(c2);
            d_cbuf[off] = c2;
            hout[off] = h2;
            __nv_bfloat16 hb1 = __float2bfloat16(h2);
            hbo[off] = hb1;
            hso[off] = __float2bfloat16(h2 - __bfloat162float(hb1));
        }
    } else {
#pragma unroll
        for (int j = 0; j < 8; j++) {
            int u = ublk * 8 + j;
            size_t off = (size_t)b * HH + (bn0 >> 2) + u;
            float h2 = hin[off];
            hout[off] = h2;
            __nv_bfloat16 hb1 = __float2bfloat16(h2);
            hbo[off] = hb1;
            hso[off] = __float2bfloat16(h2 - __bfloat162float(hb1));
        }
    }
}

// ---------------- decoder output: logits -> softmax -> argmax ----------------
__global__ __launch_bounds__(256, 2) void dec_out_kernel(
    const float* __restrict__ outW, const float* __restrict__ outb,
    float* __restrict__ dout, int out_size, int t, int parity) {
    const float* __restrict__ h = d_hbuf[parity];
    __shared__ __align__(16) float sh[4][HH];
    __shared__ float slog[4][VV];
    __shared__ float sexp[4][VV];
    __shared__ float ssum[4];
    __shared__ int   stk[4];

    int tid = threadIdx.x;
    int b0 = blockIdx.x * 4;
#pragma unroll
    for (int j = 0; j < 4; j++) {
        int idx4 = tid + 256 * j;
        int row = idx4 >> 8, c4 = idx4 & 255;
        *(float4*)&sh[row][c4 << 2] = *(const float4*)&h[(size_t)(b0 + row) * HH + (c4 << 2)];
    }
    __syncthreads();

    int v = tid & 127, half = tid >> 7;
    float a0 = 0.0f, a1 = 0.0f;
    const float* s0 = sh[half * 2];
    const float* s1 = sh[half * 2 + 1];
#pragma unroll 8
    for (int k = 0; k < HH; k++) {
        float w = outW[(size_t)k * VV + v];
        a0 += s0[k] * w;
        a1 += s1[k] * w;
    }
    float bv = outb[v];
    slog[half * 2][v]     = a0 + bv;
    slog[half * 2 + 1][v] = a1 + bv;
    __syncthreads();

    if (tid < 128) {
        int rw = tid >> 5, lane = tid & 31;
        float m = -3.4e38f; int am = VV;
#pragma unroll
        for (int i = 0; i < 4; i++) {
            int vv = lane + (i << 5);
            float x = slog[rw][vv];
            if (x > m || (x == m && vv < am)) { m = x; am = vv; }
        }
#pragma unroll
        for (int off = 16; off; off >>= 1) {
            float om = __shfl_down_sync(0xffffffffu, m, off);
            int   oa = __shfl_down_sync(0xffffffffu, am, off);
            if (om > m || (om == m && oa < am)) { m = om; am = oa; }
        }
        m  = __shfl_sync(0xffffffffu, m, 0);
        am = __shfl_sync(0xffffffffu, am, 0);
        float s = 0.0f;
#pragma unroll
        for (int i = 0; i < 4; i++) {
            int vv = lane + (i << 5);
            float e = __expf(slog[rw][vv] - m);
            sexp[rw][vv] = e;
            s += e;
        }
#pragma unroll
        for (int off = 16; off; off >>= 1) s += __shfl_xor_sync(0xffffffffu, s, off);
        if (lane == 0) { ssum[rw] = s; stk[rw] = am; d_tok[b0 + rw] = am; }
    }
    __syncthreads();
#pragma unroll
    for (int j = 0; j < 2; j++) {
        int idx = tid + 256 * j;
        int rw = idx >> 7, vv = idx & 127;
        dout[((size_t)(b0 + rw) * LL + t) * VV + vv] = sexp[rw][vv] / ssum[rw];
    }
    if (out_size >= BB * LL * VV + LL * BB && tid < 4) {
        dout[(size_t)BB * LL * VV + (size_t)t * BB + (b0 + tid)] = (float)stk[tid];
    }
}

// ---------------- launcher ----------------
extern "C" void kernel_launch(void* const* d_in, const int* in_sizes, int n_in,
                              void* d_out, int out_size) {
    int idx = 0;
    const int* inputs = (const int*)d_in[idx++];
    if (idx < n_in && in_sizes[idx] == 1) idx++;  // skip max_len scalar if present
    const float* enc_emb = (const float*)d_in[idx++];
    const float* enc_W   = (const float*)d_in[idx++];
    const float* enc_U   = (const float*)d_in[idx++];
    const float* enc_b   = (const float*)d_in[idx++];
    const float* dec_emb = (const float*)d_in[idx++];
    const float* dec_W   = (const float*)d_in[idx++];
    const float* dec_U   = (const float*)d_in[idx++];
    const float* dec_b   = (const float*)d_in[idx++];
    const float* out_W   = (const float*)d_in[idx++];
    const float* out_b   = (const float*)d_in[idx++];
    float* dout = (float*)d_out;

    cudaFuncSetAttribute(lstm_mma_kernel, cudaFuncAttributeMaxDynamicSharedMemorySize,
                         SMEM_BYTES);

    init_kernel<<<256, 256>>>();
    table_kernel<<<128, 256>>>(enc_emb, enc_W, enc_b, 0);
    table_kernel<<<128, 256>>>(dec_emb, dec_W, dec_b, 1);
    pack_kernel<<<dim3(32, 128), 256>>>(enc_U, 0);
    pack_kernel<<<dim3(32, 128), 256>>>(dec_U, 1);

    dim3 grid(64, 2);
    int par = 0;
    for (int t = 0; t < TT; t++) {
        lstm_mma_kernel<<<grid, 256, SMEM_BYTES>>>(0, inputs + t, TT, 0, par);
        par ^= 1;
    }
    for (int s = 0; s < LL; s++) {
        lstm_mma_kernel<<<grid, 256, SMEM_BYTES>>>(1, (const int*)0, 1, 1, par);
        par ^= 1;
        dec_out_kernel<<<64, 256>>>(out_W, out_b, dout, out_size, s, par);
    }
}

// round 11
// speedup vs baseline: 1.7064x; 1.0487x over previous
#include <cuda_runtime.h>
#include <cuda_bf16.h>
#include <math.h>
#include <stdint.h>

#define BB 256
#define TT 64
#define HH 1024
#define GG 4096
#define VV 128
#define LL 32

// ---------------- device state (no allocations allowed) ----------------
__device__ __align__(16) float d_hbuf[2][BB * HH];           // fp32 h
__device__ __align__(16) __nv_bfloat16 d_hbb[2][BB * HH];    // bf16 big part of h
__device__ __align__(16) __nv_bfloat16 d_hsb[2][BB * HH];    // bf16 residual of h
__device__ __align__(16) float d_cbuf[BB * HH];
__device__ __align__(16) float d_encX[VV * GG];              // [v][ku*4+g] = emb@W + b
__device__ __align__(16) float d_decX[VV * GG];
__device__ int d_tok[BB];
__device__ __align__(16) __nv_bfloat16 d_Ubb[2][(size_t)GG * HH];  // [which][pc][k] big
__device__ __align__(16) __nv_bfloat16 d_Usb[2][(size_t)GG * HH];  // residual

// ---------------- helpers ----------------
__device__ __forceinline__ float sigmoidf_(float x) { return 1.0f / (1.0f + __expf(-x)); }
__device__ __forceinline__ float tanhf_(float x) {
    float a = fabsf(x);
    float e = __expf(2.0f * a);
    return copysignf(1.0f - 2.0f / (e + 1.0f), x);
}
__device__ __forceinline__ uint32_t smem_u32(const void* p) {
    uint32_t a;
    asm("{ .reg .u64 t; cvta.to.shared.u64 t, %1; cvt.u32.u64 %0, t; }" : "=r"(a) : "l"(p));
    return a;
}
__device__ __forceinline__ void cpasync16(uint32_t dst, const void* src) {
    asm volatile("cp.async.cg.shared.global [%0], [%1], 16;"
                 :: "r"(dst), "l"(__cvta_generic_to_global(src)) : "memory");
}
__device__ __forceinline__ void mma16816(float* c, const uint32_t* a, const uint32_t* b) {
    asm volatile(
        "mma.sync.aligned.m16n8k16.row.col.f32.bf16.bf16.f32 "
        "{%0,%1,%2,%3}, {%4,%5,%6,%7}, {%8,%9}, {%0,%1,%2,%3};"
        : "+f"(c[0]), "+f"(c[1]), "+f"(c[2]), "+f"(c[3])
        : "r"(a[0]), "r"(a[1]), "r"(a[2]), "r"(a[3]), "r"(b[0]), "r"(b[1]));
}
__device__ __forceinline__ void ldsm4(uint32_t* r, uint32_t addr) {
    asm volatile("ldmatrix.sync.aligned.m8n8.x4.shared.b16 {%0,%1,%2,%3}, [%4];"
                 : "=r"(r[0]), "=r"(r[1]), "=r"(r[2]), "=r"(r[3]) : "r"(addr));
}

// ---------------- init ----------------
__global__ void init_kernel() {
    int n = BB * HH;
    __nv_bfloat16 z = __float2bfloat16(0.0f);
    for (int i = blockIdx.x * blockDim.x + threadIdx.x; i < n; i += gridDim.x * blockDim.x) {
        d_hbuf[0][i] = 0.0f;
        d_hbb[0][i] = z;
        d_hsb[0][i] = z;
        d_cbuf[i] = 0.0f;
    }
    if (blockIdx.x == 0 && threadIdx.x < BB) d_tok[threadIdx.x] = VV - 1;
}

// ---------------- table: Xp[v][ku*4+g] = emb[v]@W[:,g*1024+ku] + b ----------------
__global__ __launch_bounds__(256, 1) void table_kernel(
    const float* __restrict__ emb, const float* __restrict__ W,
    const float* __restrict__ bias, int which) {
    float* Xp = which ? d_decX : d_encX;
    __shared__ __align__(16) float semb[32][VV];
    int tid = threadIdx.x;
    int c = blockIdx.x * 32 + (tid & 31);
    int vg = tid >> 5;
    float acc[16];
#pragma unroll
    for (int j = 0; j < 16; j++) acc[j] = 0.0f;
    for (int r0 = 0; r0 < HH; r0 += 32) {
#pragma unroll
        for (int j = 0; j < 4; j++) {
            int idx4 = tid + 256 * j;
            int v = idx4 >> 3, rq = idx4 & 7;
            float4 t4 = *(const float4*)&emb[(size_t)v * HH + r0 + (rq << 2)];
            semb[(rq << 2) + 0][v] = t4.x;
            semb[(rq << 2) + 1][v] = t4.y;
            semb[(rq << 2) + 2][v] = t4.z;
            semb[(rq << 2) + 3][v] = t4.w;
        }
        __syncthreads();
#pragma unroll 8
        for (int r = 0; r < 32; r++) {
            float w = W[(size_t)(r0 + r) * GG + c];
            const float* sp = &semb[r][vg << 4];
#pragma unroll
            for (int j = 0; j < 16; j++) acc[j] += sp[j] * w;
        }
        __syncthreads();
    }
    int k = c & (HH - 1), g = c >> 10;
    float bv = bias[c];
#pragma unroll
    for (int j = 0; j < 16; j++) {
        int v = (vg << 4) + j;
        Xp[(size_t)v * GG + (k << 2) + g] = acc[j] + bv;
    }
}

// ---------------- pack U: Upk[ku*4+g][k] = U[k][g*1024+ku], bf16 split ----------------
__global__ __launch_bounds__(256, 4) void pack_kernel(const float* __restrict__ U, int which) {
    __shared__ float s[32][33];
    int tid = threadIdx.x;
    int k0 = blockIdx.x * 32;
    int c0 = blockIdx.y * 32;
#pragma unroll
    for (int j = 0; j < 4; j++) {
        int idx = tid + 256 * j;
        int r = idx >> 5, ci = idx & 31;
        s[r][ci] = U[(size_t)(k0 + r) * GG + c0 + ci];
    }
    __syncthreads();
    int g = c0 >> 10;
    int ku0 = c0 & (HH - 1);
    __nv_bfloat16* Ub = d_Ubb[which];
    __nv_bfloat16* Us = d_Usb[which];
#pragma unroll
    for (int j = 0; j < 4; j++) {
        int idx = tid + 256 * j;
        int ci = idx >> 5, r = idx & 31;
        float v = s[r][ci];
        __nv_bfloat16 bp = __float2bfloat16(v);
        size_t o = (size_t)((ku0 + ci) * 4 + g) * HH + (k0 + r);
        Ub[o] = bp;
        Us[o] = __float2bfloat16(v - __bfloat162float(bp));
    }
}

// ---------------- mma LSTM step (ldmatrix + K64 chunks) ----------------
// grid (64,2), 256 threads = 8 warps (4 m x 2 n), warp tile 32(M)x32(N packed).
// CTA: M=128 x N=64 packed; K=1024 in 16 chunks of 64.
// z = hb@Ub + hb@Us + hs@Ub (bf16x3).
#define RSTR  72           // bf16 per smem row (144B: 16B-aligned, conflict-free rotation)
#define RSTRB 144
#define OFS_AB 0u
#define OFS_AS 18432u
#define OFS_BBG 36864u
#define OFS_BS 46080u
#define BUFSZ  55296u
#define OFS_TOK 110592u
#define SMEM_BYTES 111616
#define ZSTR 68            // z epilogue stride (floats)

__device__ __forceinline__ void stage_chunk(
    uint32_t sb, int buf, int kc, int tid,
    const __nv_bfloat16* hb, const __nv_bfloat16* hs,
    const __nv_bfloat16* Ub, const __nv_bfloat16* Us, int bm0, int bn0) {
    uint32_t base = sb + buf * BUFSZ;
    int kofs = kc * 64;
#pragma unroll
    for (int j = 0; j < 4; j++) {               // A: 128 rows x 128B per part
        int idx = tid + 256 * j;
        int row = idx >> 3, c = idx & 7;
        uint32_t d = (uint32_t)(row * RSTRB + c * 16);
        size_t go = (size_t)(bm0 + row) * HH + kofs + c * 8;
        cpasync16(base + OFS_AB + d, hb + go);
        cpasync16(base + OFS_AS + d, hs + go);
    }
#pragma unroll
    for (int j = 0; j < 2; j++) {               // B: 64 rows x 128B per part
        int idx = tid + 256 * j;
        int row = idx >> 3, c = idx & 7;
        uint32_t d = (uint32_t)(row * RSTRB + c * 16);
        size_t go = (size_t)(bn0 + row) * HH + kofs + c * 8;
        cpasync16(base + OFS_BBG + d, Ub + go);
        cpasync16(base + OFS_BS + d, Us + go);
    }
}

__global__ __launch_bounds__(256, 1) void lstm_mma_kernel(
    int which, const int* __restrict__ tokptr, int tokstride, int tok_mode, int parity) {
    extern __shared__ char smem[];
    uint32_t sb = smem_u32(smem);
    int tid = threadIdx.x;
    int wid = tid >> 5, lane = tid & 31;
    int wm = wid & 3, wn = wid >> 2;            // warp tile: rows wm*32, cols wn*32
    int bn0 = blockIdx.x * 64;
    int bm0 = blockIdx.y * 128;

    const __nv_bfloat16* hb = d_hbb[parity];
    const __nv_bfloat16* hs = d_hsb[parity];
    const __nv_bfloat16* Ub = d_Ubb[which];
    const __nv_bfloat16* Us = d_Usb[which];
    int* stok = (int*)(smem + OFS_TOK);

    if (tid < 128)
        stok[tid] = tok_mode ? d_tok[bm0 + tid] : tokptr[(size_t)(bm0 + tid) * tokstride];

    float acc[2][4][4];
#pragma unroll
    for (int mt = 0; mt < 2; mt++)
#pragma unroll
        for (int nt = 0; nt < 4; nt++)
#pragma unroll
            for (int r = 0; r < 4; r++) acc[mt][nt][r] = 0.0f;

    // ldmatrix lane bases (canonical x4 mapping)
    // A: lanes 0-15 -> rows 0-15 (k 0-7), lanes 16-31 -> rows 0-15 (k 8-15)
    uint32_t a_base = sb + OFS_AB +
        (uint32_t)((wm * 32 + (lane & 15)) * RSTRB + (lane >> 4) * 16);
    // B: lanes 0-7: n0-7/k0-7; 8-15: n0-7/k8-15; 16-23: n8-15/k0-7; 24-31: n8-15/k8-15
    uint32_t b_base = sb + OFS_BBG +
        (uint32_t)((wn * 32 + ((lane >> 4) << 3) + (lane & 7)) * RSTRB + ((lane >> 3) & 1) * 16);

    stage_chunk(sb, 0, 0, tid, hb, hs, Ub, Us, bm0, bn0);
    asm volatile("cp.async.commit_group;" ::: "memory");

    for (int i = 0; i < 16; i++) {
        asm volatile("cp.async.wait_group 0;" ::: "memory");
        __syncthreads();
        if (i + 1 < 16) {
            stage_chunk(sb, (i + 1) & 1, i + 1, tid, hb, hs, Ub, Us, bm0, bn0);
            asm volatile("cp.async.commit_group;" ::: "memory");
        }
        uint32_t bofs = (uint32_t)((i & 1) * BUFSZ);
#pragma unroll
        for (int ks = 0; ks < 4; ks++) {
            uint32_t ka = bofs + ks * 32;
            uint32_t ab[2][4], as2[2][4], bbf[2][4], bsf[2][4];
            ldsm4(ab[0],  a_base + ka);
            ldsm4(ab[1],  a_base + ka + 16 * RSTRB);
            ldsm4(as2[0], a_base + ka + (OFS_AS - OFS_AB));
            ldsm4(as2[1], a_base + ka + (OFS_AS - OFS_AB) + 16 * RSTRB);
            ldsm4(bbf[0], b_base + ka);
            ldsm4(bbf[1], b_base + ka + 16 * RSTRB);
            ldsm4(bsf[0], b_base + ka + (OFS_BS - OFS_BBG));
            ldsm4(bsf[1], b_base + ka + (OFS_BS - OFS_BBG) + 16 * RSTRB);
#pragma unroll
            for (int mt = 0; mt < 2; mt++)
#pragma unroll
                for (int np = 0; np < 2; np++) {
                    mma16816(acc[mt][np * 2 + 0], ab[mt],  &bbf[np][0]);
                    mma16816(acc[mt][np * 2 + 1], ab[mt],  &bbf[np][2]);
                    mma16816(acc[mt][np * 2 + 0], ab[mt],  &bsf[np][0]);
                    mma16816(acc[mt][np * 2 + 1], ab[mt],  &bsf[np][2]);
                    mma16816(acc[mt][np * 2 + 0], as2[mt], &bbf[np][0]);
                    mma16816(acc[mt][np * 2 + 1], as2[mt], &bbf[np][2]);
                }
        }
        __syncthreads();
    }

    // ---- epilogue: z -> smem -> gates ----
    float* z = (float*)smem;   // 128 x ZSTR floats = 34816 B (buffers dead now)
    int gq = lane >> 2, tq = lane & 3;
#pragma unroll
    for (int mt = 0; mt < 2; mt++) {
        int row0 = wm * 32 + mt * 16 + gq;
#pragma unroll
        for (int nt = 0; nt < 4; nt++) {
            int col = wn * 32 + nt * 8 + 2 * tq;
            *(float2*)&z[row0 * ZSTR + col] = make_float2(acc[mt][nt][0], acc[mt][nt][1]);
            *(float2*)&z[(row0 + 8) * ZSTR + col] = make_float2(acc[mt][nt][2], acc[mt][nt][3]);
        }
    }
    __syncthreads();

    int row = tid & 127;
    int ublk = tid >> 7;                 // 0..1 -> units ublk*8 .. +7
    int b = bm0 + row;
    int tok = stok[row];
    const float* Xp = which ? d_decX : d_encX;
    const float* hin = d_hbuf[parity];
    float* hout = d_hbuf[parity ^ 1];
    __nv_bfloat16* hbo = d_hbb[parity ^ 1];
    __nv_bfloat16* hso = d_hsb[parity ^ 1];

    if (tok != 0) {
#pragma unroll
        for (int j = 0; j < 8; j++) {
            int u = ublk * 8 + j;
            int kg = (bn0 >> 2) + u;
            float4 zv = *(const float4*)&z[row * ZSTR + u * 4];
            float4 xv = *(const float4*)&Xp[(size_t)tok * GG + bn0 + u * 4];
            float zi = zv.x + xv.x, zf = zv.y + xv.y;
            float zg = zv.z + xv.z, zo = zv.w + xv.w;
            size_t off = (size_t)b * HH + kg;
            float c2 = sigmoidf_(zf) * d_cbuf[off] + sigmoidf_(zi) * tanhf_(zg);
            float h2 = sigmoidf_(zo) * tanhf_(c2);
            d_cbuf[off] = c2;
            hout[off] = h2;
            __nv_bfloat16 hb1 = __float2bfloat16(h2);
            hbo[off] = hb1;
            hso[off] = __float2bfloat16(h2 - __bfloat162float(hb1));
        }
    } else {
#pragma unroll
        for (int j = 0; j < 8; j++) {
            int u = ublk * 8 + j;
            size_t off = (size_t)b * HH + (bn0 >> 2) + u;
            float h2 = hin[off];
            hout[off] = h2;
            __nv_bfloat16 hb1 = __float2bfloat16(h2);
            hbo[off] = hb1;
            hso[off] = __float2bfloat16(h2 - __bfloat162float(hb1));
        }
    }
}

// ---------------- decoder output: logits -> softmax -> argmax ----------------
__global__ __launch_bounds__(256, 2) void dec_out_kernel(
    const float* __restrict__ outW, const float* __restrict__ outb,
    float* __restrict__ dout, int out_size, int t, int parity) {
    const float* __restrict__ h = d_hbuf[parity];
    __shared__ __align__(16) float sh[4][HH];
    __shared__ float slog[4][VV];
    __shared__ float sexp[4][VV];
    __shared__ float ssum[4];
    __shared__ int   stk[4];

    int tid = threadIdx.x;
    int b0 = blockIdx.x * 4;
#pragma unroll
    for (int j = 0; j < 4; j++) {
        int idx4 = tid + 256 * j;
        int row = idx4 >> 8, c4 = idx4 & 255;
        *(float4*)&sh[row][c4 << 2] = *(const float4*)&h[(size_t)(b0 + row) * HH + (c4 << 2)];
    }
    __syncthreads();

    int v = tid & 127, half = tid >> 7;
    float a0 = 0.0f, a1 = 0.0f;
    const float* s0 = sh[half * 2];
    const float* s1 = sh[half * 2 + 1];
#pragma unroll 8
    for (int k = 0; k < HH; k++) {
        float w = outW[(size_t)k * VV + v];
        a0 += s0[k] * w;
        a1 += s1[k] * w;
    }
    float bv = outb[v];
    slog[half * 2][v]     = a0 + bv;
    slog[half * 2 + 1][v] = a1 + bv;
    __syncthreads();

    if (tid < 128) {
        int rw = tid >> 5, lane = tid & 31;
        float m = -3.4e38f; int am = VV;
#pragma unroll
        for (int i = 0; i < 4; i++) {
            int vv = lane + (i << 5);
            float x = slog[rw][vv];
            if (x > m || (x == m && vv < am)) { m = x; am = vv; }
        }
#pragma unroll
        for (int off = 16; off; off >>= 1) {
            float om = __shfl_down_sync(0xffffffffu, m, off);
            int   oa = __shfl_down_sync(0xffffffffu, am, off);
            if (om > m || (om == m && oa < am)) { m = om; am = oa; }
        }
        m  = __shfl_sync(0xffffffffu, m, 0);
        am = __shfl_sync(0xffffffffu, am, 0);
        float s = 0.0f;
#pragma unroll
        for (int i = 0; i < 4; i++) {
            int vv = lane + (i << 5);
            float e = __expf(slog[rw][vv] - m);
            sexp[rw][vv] = e;
            s += e;
        }
#pragma unroll
        for (int off = 16; off; off >>= 1) s += __shfl_xor_sync(0xffffffffu, s, off);
        if (lane == 0) { ssum[rw] = s; stk[rw] = am; d_tok[b0 + rw] = am; }
    }
    __syncthreads();
#pragma unroll
    for (int j = 0; j < 2; j++) {
        int idx = tid + 256 * j;
        int rw = idx >> 7, vv = idx & 127;
        dout[((size_t)(b0 + rw) * LL + t) * VV + vv] = sexp[rw][vv] / ssum[rw];
    }
    if (out_size >= BB * LL * VV + LL * BB && tid < 4) {
        dout[(size_t)BB * LL * VV + (size_t)t * BB + (b0 + tid)] = (float)stk[tid];
    }
}

// ---------------- launcher ----------------
extern "C" void kernel_launch(void* const* d_in, const int* in_sizes, int n_in,
                              void* d_out, int out_size) {
    int idx = 0;
    const int* inputs = (const int*)d_in[idx++];
    if (idx < n_in && in_sizes[idx] == 1) idx++;  // skip max_len scalar if present
    const float* enc_emb = (const float*)d_in[idx++];
    const float* enc_W   = (const float*)d_in[idx++];
    const float* enc_U   = (const float*)d_in[idx++];
    const float* enc_b   = (const float*)d_in[idx++];
    const float* dec_emb = (const float*)d_in[idx++];
    const float* dec_W   = (const float*)d_in[idx++];
    const float* dec_U   = (const float*)d_in[idx++];
    const float* dec_b   = (const float*)d_in[idx++];
    const float* out_W   = (const float*)d_in[idx++];
    const float* out_b   = (const float*)d_in[idx++];
    float* dout = (float*)d_out;

    cudaFuncSetAttribute(lstm_mma_kernel, cudaFuncAttributeMaxDynamicSharedMemorySize,
                         SMEM_BYTES);

    init_kernel<<<256, 256>>>();
    table_kernel<<<128, 256>>>(enc_emb, enc_W, enc_b, 0);
    table_kernel<<<128, 256>>>(dec_emb, dec_W, dec_b, 1);
    pack_kernel<<<dim3(32, 128), 256>>>(enc_U, 0);
    pack_kernel<<<dim3(32, 128), 256>>>(dec_U, 1);

    dim3 grid(64, 2);
    int par = 0;
    for (int t = 0; t < TT; t++) {
        lstm_mma_kernel<<<grid, 256, SMEM_BYTES>>>(0, inputs + t, TT, 0, par);
        par ^= 1;
    }
    for (int s = 0; s < LL; s++) {
        lstm_mma_kernel<<<grid, 256, SMEM_BYTES>>>(1, (const int*)0, 1, 1, par);
        par ^= 1;
        dec_out_kernel<<<64, 256>>>(out_W, out_b, dout, out_size, s, par);
    }
}

// round 12
// speedup vs baseline: 1.7170x; 1.0062x over previous
#include <cuda_runtime.h>
#include <cuda_bf16.h>
#include <math.h>
#include <stdint.h>

#define BB 256
#define TT 64
#define HH 1024
#define GG 4096
#define VV 128
#define LL 32

// ---------------- device state (no allocations allowed) ----------------
__device__ __align__(16) float d_hbuf[2][BB * HH];           // fp32 h
__device__ __align__(16) __nv_bfloat16 d_hbb[2][BB * HH];    // bf16 big part of h
__device__ __align__(16) __nv_bfloat16 d_hsb[2][BB * HH];    // bf16 residual of h
__device__ __align__(16) float d_cbuf[BB * HH];
__device__ __align__(16) float d_encX[VV * GG];              // [v][ku*4+g] = emb@W + b
__device__ __align__(16) float d_decX[VV * GG];
__device__ int d_tok[BB];
__device__ __align__(16) __nv_bfloat16 d_Ubb[2][(size_t)GG * HH];  // [which][pc][k] big
__device__ __align__(16) __nv_bfloat16 d_Usb[2][(size_t)GG * HH];  // residual

// ---------------- helpers ----------------
__device__ __forceinline__ float sigmoidf_(float x) { return 1.0f / (1.0f + __expf(-x)); }
__device__ __forceinline__ float tanhf_(float x) {
    float a = fabsf(x);
    float e = __expf(2.0f * a);
    return copysignf(1.0f - 2.0f / (e + 1.0f), x);
}
__device__ __forceinline__ uint32_t smem_u32(const void* p) {
    uint32_t a;
    asm("{ .reg .u64 t; cvta.to.shared.u64 t, %1; cvt.u32.u64 %0, t; }" : "=r"(a) : "l"(p));
    return a;
}
__device__ __forceinline__ void cpasync16(uint32_t dst, const void* src) {
    asm volatile("cp.async.cg.shared.global [%0], [%1], 16;"
                 :: "r"(dst), "l"(__cvta_generic_to_global(src)) : "memory");
}
__device__ __forceinline__ void mma16816(float* c, const uint32_t* a, const uint32_t* b) {
    asm volatile(
        "mma.sync.aligned.m16n8k16.row.col.f32.bf16.bf16.f32 "
        "{%0,%1,%2,%3}, {%4,%5,%6,%7}, {%8,%9}, {%0,%1,%2,%3};"
        : "+f"(c[0]), "+f"(c[1]), "+f"(c[2]), "+f"(c[3])
        : "r"(a[0]), "r"(a[1]), "r"(a[2]), "r"(a[3]), "r"(b[0]), "r"(b[1]));
}
__device__ __forceinline__ void ldsm4(uint32_t* r, uint32_t addr) {
    asm volatile("ldmatrix.sync.aligned.m8n8.x4.shared.b16 {%0,%1,%2,%3}, [%4];"
                 : "=r"(r[0]), "=r"(r[1]), "=r"(r[2]), "=r"(r[3]) : "r"(addr));
}

// ---------------- init ----------------
__global__ void init_kernel() {
    int n = BB * HH;
    __nv_bfloat16 z = __float2bfloat16(0.0f);
    for (int i = blockIdx.x * blockDim.x + threadIdx.x; i < n; i += gridDim.x * blockDim.x) {
        d_hbuf[0][i] = 0.0f;
        d_hbb[0][i] = z;
        d_hsb[0][i] = z;
        d_cbuf[i] = 0.0f;
    }
    if (blockIdx.x == 0 && threadIdx.x < BB) d_tok[threadIdx.x] = VV - 1;
}

// ---------------- table: Xp[v][ku*4+g] = emb[v]@W[:,g*1024+ku] + b ----------------
__global__ __launch_bounds__(256, 1) void table_kernel(
    const float* __restrict__ emb, const float* __restrict__ W,
    const float* __restrict__ bias, int which) {
    float* Xp = which ? d_decX : d_encX;
    __shared__ __align__(16) float semb[32][VV];
    int tid = threadIdx.x;
    int c = blockIdx.x * 32 + (tid & 31);
    int vg = tid >> 5;
    float acc[16];
#pragma unroll
    for (int j = 0; j < 16; j++) acc[j] = 0.0f;
    for (int r0 = 0; r0 < HH; r0 += 32) {
#pragma unroll
        for (int j = 0; j < 4; j++) {
            int idx4 = tid + 256 * j;
            int v = idx4 >> 3, rq = idx4 & 7;
            float4 t4 = *(const float4*)&emb[(size_t)v * HH + r0 + (rq << 2)];
            semb[(rq << 2) + 0][v] = t4.x;
            semb[(rq << 2) + 1][v] = t4.y;
            semb[(rq << 2) + 2][v] = t4.z;
            semb[(rq << 2) + 3][v] = t4.w;
        }
        __syncthreads();
#pragma unroll 8
        for (int r = 0; r < 32; r++) {
            float w = W[(size_t)(r0 + r) * GG + c];
            const float* sp = &semb[r][vg << 4];
#pragma unroll
            for (int j = 0; j < 16; j++) acc[j] += sp[j] * w;
        }
        __syncthreads();
    }
    int k = c & (HH - 1), g = c >> 10;
    float bv = bias[c];
#pragma unroll
    for (int j = 0; j < 16; j++) {
        int v = (vg << 4) + j;
        Xp[(size_t)v * GG + (k << 2) + g] = acc[j] + bv;
    }
}

// ---------------- pack U: Upk[ku*4+g][k] = U[k][g*1024+ku], bf16 split ----------------
__global__ __launch_bounds__(256, 4) void pack_kernel(const float* __restrict__ U, int which) {
    __shared__ float s[32][33];
    int tid = threadIdx.x;
    int k0 = blockIdx.x * 32;
    int c0 = blockIdx.y * 32;
#pragma unroll
    for (int j = 0; j < 4; j++) {
        int idx = tid + 256 * j;
        int r = idx >> 5, ci = idx & 31;
        s[r][ci] = U[(size_t)(k0 + r) * GG + c0 + ci];
    }
    __syncthreads();
    int g = c0 >> 10;
    int ku0 = c0 & (HH - 1);
    __nv_bfloat16* Ub = d_Ubb[which];
    __nv_bfloat16* Us = d_Usb[which];
#pragma unroll
    for (int j = 0; j < 4; j++) {
        int idx = tid + 256 * j;
        int ci = idx >> 5, r = idx & 31;
        float v = s[r][ci];
        __nv_bfloat16 bp = __float2bfloat16(v);
        size_t o = (size_t)((ku0 + ci) * 4 + g) * HH + (k0 + r);
        Ub[o] = bp;
        Us[o] = __float2bfloat16(v - __bfloat162float(bp));
    }
}

// ---------------- mma LSTM step (ldmatrix + K64 chunks, term-major mma order) ----------
// grid (64,2), 256 threads = 8 warps (4 m x 2 n), warp tile 32(M)x32(N packed).
// CTA: M=128 x N=64 packed; K=1024 in 16 chunks of 64.
// z = hb@Ub + hb@Us + hs@Ub (bf16x3).
#define RSTR  72           // bf16 per smem row (144B: 16B-aligned, conflict-free rotation)
#define RSTRB 144
#define OFS_AB 0u
#define OFS_AS 18432u
#define OFS_BBG 36864u
#define OFS_BS 46080u
#define BUFSZ  55296u
#define OFS_TOK 110592u
#define SMEM_BYTES 111616
#define ZSTR 68            // z epilogue stride (floats)

__device__ __forceinline__ void stage_chunk(
    uint32_t sb, int buf, int kc, int tid,
    const __nv_bfloat16* hb, const __nv_bfloat16* hs,
    const __nv_bfloat16* Ub, const __nv_bfloat16* Us, int bm0, int bn0) {
    uint32_t base = sb + buf * BUFSZ;
    int kofs = kc * 64;
#pragma unroll
    for (int j = 0; j < 4; j++) {               // A: 128 rows x 128B per part
        int idx = tid + 256 * j;
        int row = idx >> 3, c = idx & 7;
        uint32_t d = (uint32_t)(row * RSTRB + c * 16);
        size_t go = (size_t)(bm0 + row) * HH + kofs + c * 8;
        cpasync16(base + OFS_AB + d, hb + go);
        cpasync16(base + OFS_AS + d, hs + go);
    }
#pragma unroll
    for (int j = 0; j < 2; j++) {               // B: 64 rows x 128B per part
        int idx = tid + 256 * j;
        int row = idx >> 3, c = idx & 7;
        uint32_t d = (uint32_t)(row * RSTRB + c * 16);
        size_t go = (size_t)(bn0 + row) * HH + kofs + c * 8;
        cpasync16(base + OFS_BBG + d, Ub + go);
        cpasync16(base + OFS_BS + d, Us + go);
    }
}

__global__ __launch_bounds__(256, 1) void lstm_mma_kernel(
    int which, const int* __restrict__ tokptr, int tokstride, int tok_mode, int parity) {
    extern __shared__ char smem[];
    uint32_t sb = smem_u32(smem);
    int tid = threadIdx.x;
    int wid = tid >> 5, lane = tid & 31;
    int wm = wid & 3, wn = wid >> 2;            // warp tile: rows wm*32, cols wn*32
    int bn0 = blockIdx.x * 64;
    int bm0 = blockIdx.y * 128;

    const __nv_bfloat16* hb = d_hbb[parity];
    const __nv_bfloat16* hs = d_hsb[parity];
    const __nv_bfloat16* Ub = d_Ubb[which];
    const __nv_bfloat16* Us = d_Usb[which];
    int* stok = (int*)(smem + OFS_TOK);

    if (tid < 128)
        stok[tid] = tok_mode ? d_tok[bm0 + tid] : tokptr[(size_t)(bm0 + tid) * tokstride];

    float acc[2][4][4];
#pragma unroll
    for (int mt = 0; mt < 2; mt++)
#pragma unroll
        for (int nt = 0; nt < 4; nt++)
#pragma unroll
            for (int r = 0; r < 4; r++) acc[mt][nt][r] = 0.0f;

    // ldmatrix lane bases (canonical x4 mapping)
    uint32_t a_base = sb + OFS_AB +
        (uint32_t)((wm * 32 + (lane & 15)) * RSTRB + (lane >> 4) * 16);
    uint32_t b_base = sb + OFS_BBG +
        (uint32_t)((wn * 32 + ((lane >> 4) << 3) + (lane & 7)) * RSTRB + ((lane >> 3) & 1) * 16);

    stage_chunk(sb, 0, 0, tid, hb, hs, Ub, Us, bm0, bn0);
    asm volatile("cp.async.commit_group;" ::: "memory");

    for (int i = 0; i < 16; i++) {
        asm volatile("cp.async.wait_group 0;" ::: "memory");
        __syncthreads();
        if (i + 1 < 16) {
            stage_chunk(sb, (i + 1) & 1, i + 1, tid, hb, hs, Ub, Us, bm0, bn0);
            asm volatile("cp.async.commit_group;" ::: "memory");
        }
        uint32_t bofs = (uint32_t)((i & 1) * BUFSZ);
#pragma unroll
        for (int ks = 0; ks < 4; ks++) {
            uint32_t ka = bofs + ks * 32;
            uint32_t ab[2][4], as2[2][4], bbf[2][4], bsf[2][4];
            ldsm4(ab[0],  a_base + ka);
            ldsm4(ab[1],  a_base + ka + 16 * RSTRB);
            ldsm4(as2[0], a_base + ka + (OFS_AS - OFS_AB));
            ldsm4(as2[1], a_base + ka + (OFS_AS - OFS_AB) + 16 * RSTRB);
            ldsm4(bbf[0], b_base + ka);
            ldsm4(bbf[1], b_base + ka + 16 * RSTRB);
            ldsm4(bsf[0], b_base + ka + (OFS_BS - OFS_BBG));
            ldsm4(bsf[1], b_base + ka + (OFS_BS - OFS_BBG) + 16 * RSTRB);
            // term-major order: 8 distinct accumulators between every reuse
#pragma unroll
            for (int mt = 0; mt < 2; mt++)
#pragma unroll
                for (int np = 0; np < 2; np++) {
                    mma16816(acc[mt][np * 2 + 0], ab[mt], &bbf[np][0]);
                    mma16816(acc[mt][np * 2 + 1], ab[mt], &bbf[np][2]);
                }
#pragma unroll
            for (int mt = 0; mt < 2; mt++)
#pragma unroll
                for (int np = 0; np < 2; np++) {
                    mma16816(acc[mt][np * 2 + 0], ab[mt], &bsf[np][0]);
                    mma16816(acc[mt][np * 2 + 1], ab[mt], &bsf[np][2]);
                }
#pragma unroll
            for (int mt = 0; mt < 2; mt++)
#pragma unroll
                for (int np = 0; np < 2; np++) {
                    mma16816(acc[mt][np * 2 + 0], as2[mt], &bbf[np][0]);
                    mma16816(acc[mt][np * 2 + 1], as2[mt], &bbf[np][2]);
                }
        }
        // no trailing __syncthreads: next iteration's barrier (after wait_group)
        // orders compute(i) before any warp stages into this buffer again.
    }

    // ---- epilogue: z -> smem -> gates ----
    float* z = (float*)smem;   // 128 x ZSTR floats = 34816 B (buffer 0 region, dead now)
    int gq = lane >> 2, tq = lane & 3;
    __syncthreads();
#pragma unroll
    for (int mt = 0; mt < 2; mt++) {
        int row0 = wm * 32 + mt * 16 + gq;
#pragma unroll
        for (int nt = 0; nt < 4; nt++) {
            int col = wn * 32 + nt * 8 + 2 * tq;
            *(float2*)&z[row0 * ZSTR + col] = make_float2(acc[mt][nt][0], acc[mt][nt][1]);
            *(float2*)&z[(row0 + 8) * ZSTR + col] = make_float2(acc[mt][nt][2], acc[mt][nt][3]);
        }
    }
    __syncthreads();

    int row = tid & 127;
    int ublk = tid >> 7;                 // 0..1 -> units ublk*8 .. +7
    int b = bm0 + row;
    int tok = stok[row];
    const float* Xp = which ? d_decX : d_encX;
    const float* hin = d_hbuf[parity];
    float* hout = d_hbuf[parity ^ 1];
    __nv_bfloat16* hbo = d_hbb[parity ^ 1];
    __nv_bfloat16* hso = d_hsb[parity ^ 1];

    if (tok != 0) {
#pragma unroll
        for (int j = 0; j < 8; j++) {
            int u = ublk * 8 + j;
            int kg = (bn0 >> 2) + u;
            float4 zv = *(const float4*)&z[row * ZSTR + u * 4];
            float4 xv = *(const float4*)&Xp[(size_t)tok * GG + bn0 + u * 4];
            float zi = zv.x + xv.x, zf = zv.y + xv.y;
            float zg = zv.z + xv.z, zo = zv.w + xv.w;
            size_t off = (size_t)b * HH + kg;
            float c2 = sigmoidf_(zf) * d_cbuf[off] + sigmoidf_(zi) * tanhf_(zg);
            float h2 = sigmoidf_(zo) * tanhf_(c2);
            d_cbuf[off] = c2;
            hout[off] = h2;
            __nv_bfloat16 hb1 = __float2bfloat16(h2);
            hbo[off] = hb1;
            hso[off] = __float2bfloat16(h2 - __bfloat162float(hb1));
        }
    } else {
#pragma unroll
        for (int j = 0; j < 8; j++) {
            int u = ublk * 8 + j;
            size_t off = (size_t)b * HH + (bn0 >> 2) + u;
            float h2 = hin[off];
            hout[off] = h2;
            __nv_bfloat16 hb1 = __float2bfloat16(h2);
            hbo[off] = hb1;
            hso[off] = __float2bfloat16(h2 - __bfloat162float(hb1));
        }
    }
}

// ---------------- decoder output: logits -> softmax -> argmax ----------------
__global__ __launch_bounds__(256, 2) void dec_out_kernel(
    const float* __restrict__ outW, const float* __restrict__ outb,
    float* __restrict__ dout, int out_size, int t, int parity) {
    const float* __restrict__ h = d_hbuf[parity];
    __shared__ __align__(16) float sh[4][HH];
    __shared__ float slog[4][VV];
    __shared__ float sexp[4][VV];
    __shared__ float ssum[4];
    __shared__ int   stk[4];

    int tid = threadIdx.x;
    int b0 = blockIdx.x * 4;
#pragma unroll
    for (int j = 0; j < 4; j++) {
        int idx4 = tid + 256 * j;
        int row = idx4 >> 8, c4 = idx4 & 255;
        *(float4*)&sh[row][c4 << 2] = *(const float4*)&h[(size_t)(b0 + row) * HH + (c4 << 2)];
    }
    __syncthreads();

    int v = tid & 127, half = tid >> 7;
    float a0 = 0.0f, a1 = 0.0f;
    const float* s0 = sh[half * 2];
    const float* s1 = sh[half * 2 + 1];
#pragma unroll 8
    for (int k = 0; k < HH; k++) {
        float w = outW[(size_t)k * VV + v];
        a0 += s0[k] * w;
        a1 += s1[k] * w;
    }
    float bv = outb[v];
    slog[half * 2][v]     = a0 + bv;
    slog[half * 2 + 1][v] = a1 + bv;
    __syncthreads();

    if (tid < 128) {
        int rw = tid >> 5, lane = tid & 31;
        float m = -3.4e38f; int am = VV;
#pragma unroll
        for (int i = 0; i < 4; i++) {
            int vv = lane + (i << 5);
            float x = slog[rw][vv];
            if (x > m || (x == m && vv < am)) { m = x; am = vv; }
        }
#pragma unroll
        for (int off = 16; off; off >>= 1) {
            float om = __shfl_down_sync(0xffffffffu, m, off);
            int   oa = __shfl_down_sync(0xffffffffu, am, off);
            if (om > m || (om == m && oa < am)) { m = om; am = oa; }
        }
        m  = __shfl_sync(0xffffffffu, m, 0);
        am = __shfl_sync(0xffffffffu, am, 0);
        float s = 0.0f;
#pragma unroll
        for (int i = 0; i < 4; i++) {
            int vv = lane + (i << 5);
            float e = __expf(slog[rw][vv] - m);
            sexp[rw][vv] = e;
            s += e;
        }
#pragma unroll
        for (int off = 16; off; off >>= 1) s += __shfl_xor_sync(0xffffffffu, s, off);
        if (lane == 0) { ssum[rw] = s; stk[rw] = am; d_tok[b0 + rw] = am; }
    }
    __syncthreads();
#pragma unroll
    for (int j = 0; j < 2; j++) {
        int idx = tid + 256 * j;
        int rw = idx >> 7, vv = idx & 127;
        dout[((size_t)(b0 + rw) * LL + t) * VV + vv] = sexp[rw][vv] / ssum[rw];
    }
    if (out_size >= BB * LL * VV + LL * BB && tid < 4) {
        dout[(size_t)BB * LL * VV + (size_t)t * BB + (b0 + tid)] = (float)stk[tid];
    }
}

// ---------------- launcher ----------------
extern "C" void kernel_launch(void* const* d_in, const int* in_sizes, int n_in,
                              void* d_out, int out_size) {
    int idx = 0;
    const int* inputs = (const int*)d_in[idx++];
    if (idx < n_in && in_sizes[idx] == 1) idx++;  // skip max_len scalar if present
    const float* enc_emb = (const float*)d_in[idx++];
    const float* enc_W   = (const float*)d_in[idx++];
    const float* enc_U   = (const float*)d_in[idx++];
    const float* enc_b   = (const float*)d_in[idx++];
    const float* dec_emb = (const float*)d_in[idx++];
    const float* dec_W   = (const float*)d_in[idx++];
    const float* dec_U   = (const float*)d_in[idx++];
    const float* dec_b   = (const float*)d_in[idx++];
    const float* out_W   = (const float*)d_in[idx++];
    const float* out_b   = (const float*)d_in[idx++];
    float* dout = (float*)d_out;

    cudaFuncSetAttribute(lstm_mma_kernel, cudaFuncAttributeMaxDynamicSharedMemorySize,
                         SMEM_BYTES);

    init_kernel<<<256, 256>>>();
    table_kernel<<<128, 256>>>(enc_emb, enc_W, enc_b, 0);
    table_kernel<<<128, 256>>>(dec_emb, dec_W, dec_b, 1);
    pack_kernel<<<dim3(32, 128), 256>>>(enc_U, 0);
    pack_kernel<<<dim3(32, 128), 256>>>(dec_U, 1);

    dim3 grid(64, 2);
    int par = 0;
    for (int t = 0; t < TT; t++) {
        lstm_mma_kernel<<<grid, 256, SMEM_BYTES>>>(0, inputs + t, TT, 0, par);
        par ^= 1;
    }
    for (int s = 0; s < LL; s++) {
        lstm_mma_kernel<<<grid, 256, SMEM_BYTES>>>(1, (const int*)0, 1, 1, par);
        par ^= 1;
        dec_out_kernel<<<64, 256>>>(out_W, out_b, dout, out_size, s, par);
    }
}

// round 13
// speedup vs baseline: 1.9174x; 1.1167x over previous
#include <cuda_runtime.h>
#include <cuda_bf16.h>
#include <math.h>
#include <stdint.h>

#define BB 256
#define TT 64
#define HH 1024
#define GG 4096
#define VV 128
#define LL 32

// ---------------- device state (no allocations allowed) ----------------
__device__ __align__(16) float d_hbuf[2][BB * HH];           // fp32 h
__device__ __align__(16) __nv_bfloat16 d_hbb[2][BB * HH];    // bf16 big part of h
__device__ __align__(16) __nv_bfloat16 d_hsb[2][BB * HH];    // bf16 residual of h
__device__ __align__(16) float d_cbuf[BB * HH];
__device__ __align__(16) float d_encX[VV * GG];              // [v][ku*4+g] = emb@W + b
__device__ __align__(16) float d_decX[VV * GG];
__device__ int d_tok[BB];
__device__ __align__(16) __nv_bfloat16 d_Ubb[2][(size_t)GG * HH];  // [which][pc][k] big
__device__ __align__(16) __nv_bfloat16 d_Usb[2][(size_t)GG * HH];  // residual

// ---------------- helpers ----------------
__device__ __forceinline__ float sigmoidf_(float x) { return 1.0f / (1.0f + __expf(-x)); }
__device__ __forceinline__ float tanhf_(float x) {
    float a = fabsf(x);
    float e = __expf(2.0f * a);
    return copysignf(1.0f - 2.0f / (e + 1.0f), x);
}
__device__ __forceinline__ uint32_t smem_u32(const void* p) {
    uint32_t a;
    asm("{ .reg .u64 t; cvta.to.shared.u64 t, %1; cvt.u32.u64 %0, t; }" : "=r"(a) : "l"(p));
    return a;
}
__device__ __forceinline__ void cpasync16(uint32_t dst, const void* src) {
    asm volatile("cp.async.cg.shared.global [%0], [%1], 16;"
                 :: "r"(dst), "l"(__cvta_generic_to_global(src)) : "memory");
}
__device__ __forceinline__ void mma16816(float* c, const uint32_t* a, const uint32_t* b) {
    asm volatile(
        "mma.sync.aligned.m16n8k16.row.col.f32.bf16.bf16.f32 "
        "{%0,%1,%2,%3}, {%4,%5,%6,%7}, {%8,%9}, {%0,%1,%2,%3};"
        : "+f"(c[0]), "+f"(c[1]), "+f"(c[2]), "+f"(c[3])
        : "r"(a[0]), "r"(a[1]), "r"(a[2]), "r"(a[3]), "r"(b[0]), "r"(b[1]));
}
__device__ __forceinline__ void ldsm4(uint32_t* r, uint32_t addr) {
    asm volatile("ldmatrix.sync.aligned.m8n8.x4.shared.b16 {%0,%1,%2,%3}, [%4];"
                 : "=r"(r[0]), "=r"(r[1]), "=r"(r[2]), "=r"(r[3]) : "r"(addr));
}

// ---------------- init ----------------
__global__ void init_kernel() {
    int n = BB * HH;
    __nv_bfloat16 z = __float2bfloat16(0.0f);
    for (int i = blockIdx.x * blockDim.x + threadIdx.x; i < n; i += gridDim.x * blockDim.x) {
        d_hbuf[0][i] = 0.0f;
        d_hbb[0][i] = z;
        d_hsb[0][i] = z;
        d_cbuf[i] = 0.0f;
    }
    if (blockIdx.x == 0 && threadIdx.x < BB) d_tok[threadIdx.x] = VV - 1;
}

// ---------------- table: Xp[v][ku*4+g] = emb[v]@W[:,g*1024+ku] + b ----------------
__global__ __launch_bounds__(256, 1) void table_kernel(
    const float* __restrict__ emb, const float* __restrict__ W,
    const float* __restrict__ bias, int which) {
    float* Xp = which ? d_decX : d_encX;
    __shared__ __align__(16) float semb[32][VV];
    int tid = threadIdx.x;
    int c = blockIdx.x * 32 + (tid & 31);
    int vg = tid >> 5;
    float acc[16];
#pragma unroll
    for (int j = 0; j < 16; j++) acc[j] = 0.0f;
    for (int r0 = 0; r0 < HH; r0 += 32) {
#pragma unroll
        for (int j = 0; j < 4; j++) {
            int idx4 = tid + 256 * j;
            int v = idx4 >> 3, rq = idx4 & 7;
            float4 t4 = *(const float4*)&emb[(size_t)v * HH + r0 + (rq << 2)];
            semb[(rq << 2) + 0][v] = t4.x;
            semb[(rq << 2) + 1][v] = t4.y;
            semb[(rq << 2) + 2][v] = t4.z;
            semb[(rq << 2) + 3][v] = t4.w;
        }
        __syncthreads();
#pragma unroll 8
        for (int r = 0; r < 32; r++) {
            float w = W[(size_t)(r0 + r) * GG + c];
            const float* sp = &semb[r][vg << 4];
#pragma unroll
            for (int j = 0; j < 16; j++) acc[j] += sp[j] * w;
        }
        __syncthreads();
    }
    int k = c & (HH - 1), g = c >> 10;
    float bv = bias[c];
#pragma unroll
    for (int j = 0; j < 16; j++) {
        int v = (vg << 4) + j;
        Xp[(size_t)v * GG + (k << 2) + g] = acc[j] + bv;
    }
}

// ---------------- pack U: Upk[ku*4+g][k] = U[k][g*1024+ku], bf16 split ----------------
__global__ __launch_bounds__(256, 4) void pack_kernel(const float* __restrict__ U, int which) {
    __shared__ float s[32][33];
    int tid = threadIdx.x;
    int k0 = blockIdx.x * 32;
    int c0 = blockIdx.y * 32;
#pragma unroll
    for (int j = 0; j < 4; j++) {
        int idx = tid + 256 * j;
        int r = idx >> 5, ci = idx & 31;
        s[r][ci] = U[(size_t)(k0 + r) * GG + c0 + ci];
    }
    __syncthreads();
    int g = c0 >> 10;
    int ku0 = c0 & (HH - 1);
    __nv_bfloat16* Ub = d_Ubb[which];
    __nv_bfloat16* Us = d_Usb[which];
#pragma unroll
    for (int j = 0; j < 4; j++) {
        int idx = tid + 256 * j;
        int ci = idx >> 5, r = idx & 31;
        float v = s[r][ci];
        __nv_bfloat16 bp = __float2bfloat16(v);
        size_t o = (size_t)((ku0 + ci) * 4 + g) * HH + (k0 + r);
        Ub[o] = bp;
        Us[o] = __float2bfloat16(v - __bfloat162float(bp));
    }
}

// ---------------- mma LSTM step (512 threads, 16 warps: 4m x 4n) ----------------
// CTA: M=128 x N=64 packed; warp tile 32(M)x16(N); K=1024 in 16 chunks of 64.
// z = hb@Ub + hb@Us + hs@Ub (bf16x3).
#define RSTR  72           // bf16 per smem row (144B: 16B-aligned, conflict-free rotation)
#define RSTRB 144
#define OFS_AB 0u
#define OFS_AS 18432u
#define OFS_BBG 36864u
#define OFS_BS 46080u
#define BUFSZ  55296u
#define OFS_TOK 110592u
#define SMEM_BYTES 111616
#define ZSTR 68            // z epilogue stride (floats)

__device__ __forceinline__ void stage_chunk(
    uint32_t sb, int buf, int kc, int tid,
    const __nv_bfloat16* hb, const __nv_bfloat16* hs,
    const __nv_bfloat16* Ub, const __nv_bfloat16* Us, int bm0, int bn0) {
    uint32_t base = sb + buf * BUFSZ;
    int kofs = kc * 64;
#pragma unroll
    for (int j = 0; j < 2; j++) {               // A: 128 rows x 128B per part
        int idx = tid + 512 * j;
        int row = idx >> 3, c = idx & 7;
        uint32_t d = (uint32_t)(row * RSTRB + c * 16);
        size_t go = (size_t)(bm0 + row) * HH + kofs + c * 8;
        cpasync16(base + OFS_AB + d, hb + go);
        cpasync16(base + OFS_AS + d, hs + go);
    }
    {                                           // B: 64 rows x 128B per part
        int row = tid >> 3, c = tid & 7;
        uint32_t d = (uint32_t)(row * RSTRB + c * 16);
        size_t go = (size_t)(bn0 + row) * HH + kofs + c * 8;
        cpasync16(base + OFS_BBG + d, Ub + go);
        cpasync16(base + OFS_BS + d, Us + go);
    }
}

__global__ __launch_bounds__(512, 1) void lstm_mma_kernel(
    int which, const int* __restrict__ tokptr, int tokstride, int tok_mode, int parity) {
    extern __shared__ char smem[];
    uint32_t sb = smem_u32(smem);
    int tid = threadIdx.x;
    int wid = tid >> 5, lane = tid & 31;
    int wm = wid & 3, wn = wid >> 2;            // 4m x 4n; warp tile rows wm*32, cols wn*16
    int bn0 = blockIdx.x * 64;
    int bm0 = blockIdx.y * 128;

    const __nv_bfloat16* hb = d_hbb[parity];
    const __nv_bfloat16* hs = d_hsb[parity];
    const __nv_bfloat16* Ub = d_Ubb[which];
    const __nv_bfloat16* Us = d_Usb[which];
    int* stok = (int*)(smem + OFS_TOK);

    if (tid < 128)
        stok[tid] = tok_mode ? d_tok[bm0 + tid] : tokptr[(size_t)(bm0 + tid) * tokstride];

    float acc[2][2][4];
#pragma unroll
    for (int mt = 0; mt < 2; mt++)
#pragma unroll
        for (int np = 0; np < 2; np++)
#pragma unroll
            for (int r = 0; r < 4; r++) acc[mt][np][r] = 0.0f;

    // ldmatrix lane bases (canonical x4 mapping)
    uint32_t a_base = sb + OFS_AB +
        (uint32_t)((wm * 32 + (lane & 15)) * RSTRB + (lane >> 4) * 16);
    // B: one ldsm4 covers 16 n-rows x 16 k:
    // r0=(n0-7,k0-7) r1=(n0-7,k8-15) r2=(n8-15,k0-7) r3=(n8-15,k8-15)
    uint32_t b_base = sb + OFS_BBG +
        (uint32_t)((wn * 16 + ((lane >> 4) << 3) + (lane & 7)) * RSTRB + ((lane >> 3) & 1) * 16);

    stage_chunk(sb, 0, 0, tid, hb, hs, Ub, Us, bm0, bn0);
    asm volatile("cp.async.commit_group;" ::: "memory");

    for (int i = 0; i < 16; i++) {
        asm volatile("cp.async.wait_group 0;" ::: "memory");
        __syncthreads();
        if (i + 1 < 16) {
            stage_chunk(sb, (i + 1) & 1, i + 1, tid, hb, hs, Ub, Us, bm0, bn0);
            asm volatile("cp.async.commit_group;" ::: "memory");
        }
        uint32_t bofs = (uint32_t)((i & 1) * BUFSZ);
#pragma unroll
        for (int ks = 0; ks < 4; ks++) {
            uint32_t ka = bofs + ks * 32;
            uint32_t ab[2][4], as2[2][4], bb[4], bs[4];
            ldsm4(ab[0],  a_base + ka);
            ldsm4(ab[1],  a_base + ka + 16 * RSTRB);
            ldsm4(as2[0], a_base + ka + (OFS_AS - OFS_AB));
            ldsm4(as2[1], a_base + ka + (OFS_AS - OFS_AB) + 16 * RSTRB);
            ldsm4(bb, b_base + ka);
            ldsm4(bs, b_base + ka + (OFS_BS - OFS_BBG));
            // term-major: 4 distinct accumulators between reuses
#pragma unroll
            for (int mt = 0; mt < 2; mt++)
#pragma unroll
                for (int np = 0; np < 2; np++)
                    mma16816(acc[mt][np], ab[mt], &bb[np * 2]);
#pragma unroll
            for (int mt = 0; mt < 2; mt++)
#pragma unroll
                for (int np = 0; np < 2; np++)
                    mma16816(acc[mt][np], ab[mt], &bs[np * 2]);
#pragma unroll
            for (int mt = 0; mt < 2; mt++)
#pragma unroll
                for (int np = 0; np < 2; np++)
                    mma16816(acc[mt][np], as2[mt], &bb[np * 2]);
        }
    }

    // ---- epilogue: z -> smem -> gates ----
    float* z = (float*)smem;   // 128 x ZSTR floats = 34816 B (buffers dead; below OFS_TOK)
    int gq = lane >> 2, tq = lane & 3;
    __syncthreads();
#pragma unroll
    for (int mt = 0; mt < 2; mt++) {
        int row0 = wm * 32 + mt * 16 + gq;
#pragma unroll
        for (int np = 0; np < 2; np++) {
            int col = wn * 16 + np * 8 + 2 * tq;
            *(float2*)&z[row0 * ZSTR + col] = make_float2(acc[mt][np][0], acc[mt][np][1]);
            *(float2*)&z[(row0 + 8) * ZSTR + col] = make_float2(acc[mt][np][2], acc[mt][np][3]);
        }
    }
    __syncthreads();

    int row = tid & 127;
    int ublk = tid >> 7;                 // 0..3 -> units ublk*4 .. +3
    int b = bm0 + row;
    int tok = stok[row];
    const float* Xp = which ? d_decX : d_encX;
    const float* hin = d_hbuf[parity];
    float* hout = d_hbuf[parity ^ 1];
    __nv_bfloat16* hbo = d_hbb[parity ^ 1];
    __nv_bfloat16* hso = d_hsb[parity ^ 1];

    if (tok != 0) {
#pragma unroll
        for (int j = 0; j < 4; j++) {
            int u = ublk * 4 + j;
            int kg = (bn0 >> 2) + u;
            float4 zv = *(const float4*)&z[row * ZSTR + u * 4];
            float4 xv = *(const float4*)&Xp[(size_t)tok * GG + bn0 + u * 4];
            float zi = zv.x + xv.x, zf = zv.y + xv.y;
            float zg = zv.z + xv.z, zo = zv.w + xv.w;
            size_t off = (size_t)b * HH + kg;
            float c2 = sigmoidf_(zf) * d_cbuf[off] + sigmoidf_(zi) * tanhf_(zg);
            float h2 = sigmoidf_(zo) * tanhf_(c2);
            d_cbuf[off] = c2;
            hout[off] = h2;
            __nv_bfloat16 hb1 = __float2bfloat16(h2);
            hbo[off] = hb1;
            hso[off] = __float2bfloat16(h2 - __bfloat162float(hb1));
        }
    } else {
#pragma unroll
        for (int j = 0; j < 4; j++) {
            int u = ublk * 4 + j;
            size_t off = (size_t)b * HH + (bn0 >> 2) + u;
            float h2 = hin[off];
            hout[off] = h2;
            __nv_bfloat16 hb1 = __float2bfloat16(h2);
            hbo[off] = hb1;
            hso[off] = __float2bfloat16(h2 - __bfloat162float(hb1));
        }
    }
}

// ---------------- decoder output: logits -> softmax -> argmax ----------------
__global__ __launch_bounds__(256, 2) void dec_out_kernel(
    const float* __restrict__ outW, const float* __restrict__ outb,
    float* __restrict__ dout, int out_size, int t, int parity) {
    const float* __restrict__ h = d_hbuf[parity];
    __shared__ __align__(16) float sh[4][HH];
    __shared__ float slog[4][VV];
    __shared__ float sexp[4][VV];
    __shared__ float ssum[4];
    __shared__ int   stk[4];

    int tid = threadIdx.x;
    int b0 = blockIdx.x * 4;
#pragma unroll
    for (int j = 0; j < 4; j++) {
        int idx4 = tid + 256 * j;
        int row = idx4 >> 8, c4 = idx4 & 255;
        *(float4*)&sh[row][c4 << 2] = *(const float4*)&h[(size_t)(b0 + row) * HH + (c4 << 2)];
    }
    __syncthreads();

    int v = tid & 127, half = tid >> 7;
    float a0 = 0.0f, a1 = 0.0f;
    const float* s0 = sh[half * 2];
    const float* s1 = sh[half * 2 + 1];
#pragma unroll 8
    for (int k = 0; k < HH; k++) {
        float w = outW[(size_t)k * VV + v];
        a0 += s0[k] * w;
        a1 += s1[k] * w;
    }
    float bv = outb[v];
    slog[half * 2][v]     = a0 + bv;
    slog[half * 2 + 1][v] = a1 + bv;
    __syncthreads();

    if (tid < 128) {
        int rw = tid >> 5, lane = tid & 31;
        float m = -3.4e38f; int am = VV;
#pragma unroll
        for (int i = 0; i < 4; i++) {
            int vv = lane + (i << 5);
            float x = slog[rw][vv];
            if (x > m || (x == m && vv < am)) { m = x; am = vv; }
        }
#pragma unroll
        for (int off = 16; off; off >>= 1) {
            float om = __shfl_down_sync(0xffffffffu, m, off);
            int   oa = __shfl_down_sync(0xffffffffu, am, off);
            if (om > m || (om == m && oa < am)) { m = om; am = oa; }
        }
        m  = __shfl_sync(0xffffffffu, m, 0);
        am = __shfl_sync(0xffffffffu, am, 0);
        float s = 0.0f;
#pragma unroll
        for (int i = 0; i < 4; i++) {
            int vv = lane + (i << 5);
            float e = __expf(slog[rw][vv] - m);
            sexp[rw][vv] = e;
            s += e;
        }
#pragma unroll
        for (int off = 16; off; off >>= 1) s += __shfl_xor_sync(0xffffffffu, s, off);
        if (lane == 0) { ssum[rw] = s; stk[rw] = am; d_tok[b0 + rw] = am; }
    }
    __syncthreads();
#pragma unroll
    for (int j = 0; j < 2; j++) {
        int idx = tid + 256 * j;
        int rw = idx >> 7, vv = idx & 127;
        dout[((size_t)(b0 + rw) * LL + t) * VV + vv] = sexp[rw][vv] / ssum[rw];
    }
    if (out_size >= BB * LL * VV + LL * BB && tid < 4) {
        dout[(size_t)BB * LL * VV + (size_t)t * BB + (b0 + tid)] = (float)stk[tid];
    }
}

// ---------------- launcher ----------------
extern "C" void kernel_launch(void* const* d_in, const int* in_sizes, int n_in,
                              void* d_out, int out_size) {
    int idx = 0;
    const int* inputs = (const int*)d_in[idx++];
    if (idx < n_in && in_sizes[idx] == 1) idx++;  // skip max_len scalar if present
    const float* enc_emb = (const float*)d_in[idx++];
    const float* enc_W   = (const float*)d_in[idx++];
    const float* enc_U   = (const float*)d_in[idx++];
    const float* enc_b   = (const float*)d_in[idx++];
    const float* dec_emb = (const float*)d_in[idx++];
    const float* dec_W   = (const float*)d_in[idx++];
    const float* dec_U   = (const float*)d_in[idx++];
    const float* dec_b   = (const float*)d_in[idx++];
    const float* out_W   = (const float*)d_in[idx++];
    const float* out_b   = (const float*)d_in[idx++];
    float* dout = (float*)d_out;

    cudaFuncSetAttribute(lstm_mma_kernel, cudaFuncAttributeMaxDynamicSharedMemorySize,
                         SMEM_BYTES);

    init_kernel<<<256, 256>>>();
    table_kernel<<<128, 256>>>(enc_emb, enc_W, enc_b, 0);
    table_kernel<<<128, 256>>>(dec_emb, dec_W, dec_b, 1);
    pack_kernel<<<dim3(32, 128), 256>>>(enc_U, 0);
    pack_kernel<<<dim3(32, 128), 256>>>(dec_U, 1);

    dim3 grid(64, 2);
    int par = 0;
    for (int t = 0; t < TT; t++) {
        lstm_mma_kernel<<<grid, 512, SMEM_BYTES>>>(0, inputs + t, TT, 0, par);
        par ^= 1;
    }
    for (int s = 0; s < LL; s++) {
        lstm_mma_kernel<<<grid, 512, SMEM_BYTES>>>(1, (const int*)0, 1, 1, par);
        par ^= 1;
        dec_out_kernel<<<64, 256>>>(out_W, out_b, dout, out_size, s, par);
    }
}